// round 5
// baseline (speedup 1.0000x reference)
#include <cuda_runtime.h>
#include <math.h>
#include <stdint.h>

// ---------------------------------------------------------------------------
// GraphSAGE (mean -> max -> lstm aggr -> JK bi-LSTM), N=50000, K=16, C=128.
// Round 5: gates fused into recurrent GEMM epilogue (gate-interleaved weights),
// cp.async 3-stage tf32 mma pipeline, ping-pong recurrent state.
// ---------------------------------------------------------------------------

#define NN 50000
#define KK 16
#define EE (NN * KK)
#define CC 128
#define JKH 192

#define BM 128
#define BN 128
#define BKT 32
#define ASTR 36
#define AW (BM * ASTR)
#define BW (BN * ASTR)
#define SW (AW + BW)
#define SMEM_BYTES (3 * SW * 4)   // 110592 >= 128*128*4 epilogue staging

// ---------------- static device scratch -------------------------------------
__device__ int   d_src[EE];
__device__ int   d_is64;
__device__ float d_xr[NN * CC];
__device__ float d_agg[NN * CC];
__device__ float d_xcat[3 * NN * CC];           // h1 | h2 | h3
__device__ float d_hA[NN * CC];
__device__ float d_hB[NN * CC];
__device__ float d_cA[NN * CC];
__device__ float d_Pa[NN * 512];
__device__ float d_Pf[3 * NN * 768];
__device__ float d_Pb[3 * NN * 768];
__device__ float d_fwd[3 * NN * JKH];
__device__ float d_bwdp[3 * NN * JKH];
__device__ float d_cF[NN * JKH];
__device__ float d_cB[NN * JKH];
__device__ float d_w[NN * 3];
__device__ float d_wr[724000];                  // rounded/permuted weights arena

__device__ __forceinline__ float sigmoidf_(float x) { return 1.f / (1.f + expf(-x)); }

__device__ __forceinline__ uint32_t f2tf32(float f) {
    uint32_t u;
    asm("cvt.rna.tf32.f32 %0, %1;" : "=r"(u) : "f"(f));
    return u;
}
__device__ __forceinline__ float roundtf(float f) { return __uint_as_float(f2tf32(f)); }

// ---------------- edge-index probe + convert ---------------------------------
__global__ void detect_idx_kernel(const void* ei) {
    const long long* p = (const long long*)ei;
    int lane = threadIdx.x;
    int ok = 1;
#pragma unroll
    for (int i = 0; i < 4; ++i) {
        long long v = p[lane * 4 + i];
        if (v < 0 || v >= NN) ok = 0;
    }
    unsigned m = __ballot_sync(0xffffffffu, ok);
    if (lane == 0) d_is64 = (m == 0xffffffffu) ? 1 : 0;
}

__global__ void convert_src_kernel(const void* ei) {
    int idx = blockIdx.x * blockDim.x + threadIdx.x;
    if (idx >= EE) return;
    if (d_is64) d_src[idx] = (int)((const long long*)ei)[idx];
    else        d_src[idx] = ((const int*)ei)[idx];
}

// ---------------- tf32 rounding / permuting prep -----------------------------
__global__ void round_kernel(const float* __restrict__ in, float* __restrict__ out, int n4) {
    int i = blockIdx.x * blockDim.x + threadIdx.x;
    if (i >= n4) return;
    float4 v = ((const float4*)in)[i];
    v.x = roundtf(v.x); v.y = roundtf(v.y); v.z = roundtf(v.z); v.w = roundtf(v.w);
    ((float4*)out)[i] = v;
}

// out row (4c+g) = round(in row (g*H+c)); K4 = K/4 float4s per row
__global__ void permute_round_kernel(const float* __restrict__ in, float* __restrict__ out,
                                     int H, int K4) {
    int idx = blockIdx.x * blockDim.x + threadIdx.x;
    if (idx >= 4 * H * K4) return;
    int r = idx / K4, kq = idx - r * K4;
    int c = r >> 2, g = r & 3;
    float4 v = ((const float4*)in)[(size_t)(g * H + c) * K4 + kq];
    v.x = roundtf(v.x); v.y = roundtf(v.y); v.z = roundtf(v.z); v.w = roundtf(v.w);
    ((float4*)out)[(size_t)r * K4 + kq] = v;
}

__global__ void bias_comb_kernel(const float* __restrict__ bih, const float* __restrict__ bhh,
                                 float* __restrict__ out, int H) {
    int idx = blockIdx.x * blockDim.x + threadIdx.x;
    if (idx >= 4 * H) return;
    int c = idx >> 2, g = idx & 3;
    out[idx] = bih[g * H + c] + bhh[g * H + c];
}

// ---------------- neighbor aggregations --------------------------------------
__global__ void agg_mean_kernel(const float* __restrict__ X, float* __restrict__ out) {
    int idx = blockIdx.x * blockDim.x + threadIdx.x;
    if (idx >= NN * CC) return;
    int n = idx >> 7, c = idx & 127;
    const int* s = d_src + n * KK;
    float acc = 0.f;
#pragma unroll
    for (int j = 0; j < KK; ++j) acc += X[(size_t)s[j] * CC + c];
    out[idx] = roundtf(acc * (1.f / 16.f));
}

__global__ void agg_max_kernel(const float* __restrict__ X, float* __restrict__ out) {
    int idx = blockIdx.x * blockDim.x + threadIdx.x;
    if (idx >= NN * CC) return;
    int n = idx >> 7, c = idx & 127;
    const int* s = d_src + n * KK;
    float acc = -INFINITY;
#pragma unroll
    for (int j = 0; j < KK; ++j) acc = fmaxf(acc, X[(size_t)s[j] * CC + c]);
    out[idx] = roundtf(acc);
}

// ---------------- plain tf32 GEMM (cp.async 3-stage) --------------------------
// Cout = act( A@W1^T + B2@W2^T + bias ); flags: bit0 relu, bit1 round-output
__global__ __launch_bounds__(256, 2) void tf32_gemm_kernel(
    const float* __restrict__ A, const float* __restrict__ B2,
    const float* __restrict__ W1, const float* __restrict__ W2,
    const float* __restrict__ bias, float* __restrict__ Cout,
    int M, int Nc, int K1, int K2, int flags)
{
    extern __shared__ __align__(16) float sm[];
    const int tid = threadIdx.x, wid = tid >> 5, lane = tid & 31;
    const int grp = lane >> 2, tig = lane & 3;
    const int warpM = wid >> 1, warpN = wid & 1;
    const int rowBase = blockIdx.x * BM, colBase = blockIdx.y * BN;
    const int Ktot = K1 + K2, nk = Ktot / BKT;
    const int cr = tid >> 3, ck = (tid & 7) * 4;

    float c[2][8][4];
#pragma unroll
    for (int mt = 0; mt < 2; ++mt)
#pragma unroll
        for (int nt = 0; nt < 8; ++nt)
#pragma unroll
            for (int i = 0; i < 4; ++i) c[mt][nt][i] = 0.f;

    auto issue = [&](int it, int s) {
        if (it < nk) {
            int kk = it * BKT;
            const float* asrc; const float* wsrc; int ld, kb;
            if (kk < K1) { asrc = A;  wsrc = W1; ld = K1; kb = kk; }
            else         { asrc = B2; wsrc = W2; ld = K2; kb = kk - K1; }
            float* smA = sm + s * SW;
            float* smB = smA + AW;
#pragma unroll
            for (int p = 0; p < 4; ++p) {
                int r = cr + p * 32;
                int row = rowBase + r;
                int rc = (row < M) ? row : 0;
                uint32_t dst = (uint32_t)__cvta_generic_to_shared(smA + r * ASTR + ck);
                const float* g = asrc + (size_t)rc * ld + kb + ck;
                int sz = (row < M) ? 16 : 0;
                asm volatile("cp.async.cg.shared.global [%0], [%1], 16, %2;\n"
                             :: "r"(dst), "l"(g), "r"(sz));
            }
#pragma unroll
            for (int p = 0; p < 4; ++p) {
                int r = cr + p * 32;
                uint32_t dst = (uint32_t)__cvta_generic_to_shared(smB + r * ASTR + ck);
                const float* g = wsrc + (size_t)(colBase + r) * ld + kb + ck;
                asm volatile("cp.async.cg.shared.global [%0], [%1], 16;\n"
                             :: "r"(dst), "l"(g));
            }
        }
        asm volatile("cp.async.commit_group;\n");
    };

    issue(0, 0);
    issue(1, 1);

    for (int it = 0; it < nk; ++it) {
        asm volatile("cp.async.wait_group 1;\n");
        __syncthreads();
        const int s = it % 3;
        const float* smA = sm + s * SW;
        const float* smB = smA + AW;
        const int m0 = warpM * 32, n0 = warpN * 64;
#pragma unroll
        for (int kt = 0; kt < 4; ++kt) {
            const int k0 = kt * 8;
            uint32_t af[2][4], bf[8][2];
#pragma unroll
            for (int mt = 0; mt < 2; ++mt) {
                int m = m0 + mt * 16;
                af[mt][0] = __float_as_uint(smA[(m + grp) * ASTR + k0 + tig]);
                af[mt][1] = __float_as_uint(smA[(m + 8 + grp) * ASTR + k0 + tig]);
                af[mt][2] = __float_as_uint(smA[(m + grp) * ASTR + k0 + tig + 4]);
                af[mt][3] = __float_as_uint(smA[(m + 8 + grp) * ASTR + k0 + tig + 4]);
            }
#pragma unroll
            for (int nt = 0; nt < 8; ++nt) {
                int n = n0 + nt * 8;
                bf[nt][0] = __float_as_uint(smB[(n + grp) * ASTR + k0 + tig]);
                bf[nt][1] = __float_as_uint(smB[(n + grp) * ASTR + k0 + tig + 4]);
            }
#pragma unroll
            for (int mt = 0; mt < 2; ++mt)
#pragma unroll
                for (int nt = 0; nt < 8; ++nt) {
                    asm volatile(
                        "mma.sync.aligned.m16n8k8.row.col.f32.tf32.tf32.f32 "
                        "{%0,%1,%2,%3}, {%4,%5,%6,%7}, {%8,%9}, {%0,%1,%2,%3};\n"
                        : "+f"(c[mt][nt][0]), "+f"(c[mt][nt][1]),
                          "+f"(c[mt][nt][2]), "+f"(c[mt][nt][3])
                        : "r"(af[mt][0]), "r"(af[mt][1]), "r"(af[mt][2]), "r"(af[mt][3]),
                          "r"(bf[nt][0]), "r"(bf[nt][1]));
                }
        }
        issue(it + 2, (it + 2) % 3);
    }

    const int do_relu = flags & 1, do_round = flags & 2;
#pragma unroll
    for (int mt = 0; mt < 2; ++mt) {
#pragma unroll
        for (int nt = 0; nt < 8; ++nt) {
            int col = colBase + warpN * 64 + nt * 8 + tig * 2;
            float b0 = bias ? bias[col] : 0.f;
            float b1 = bias ? bias[col + 1] : 0.f;
            int r0 = rowBase + warpM * 32 + mt * 16 + grp;
            int r1 = r0 + 8;
            float v0 = c[mt][nt][0] + b0, v1 = c[mt][nt][1] + b1;
            float v2 = c[mt][nt][2] + b0, v3 = c[mt][nt][3] + b1;
            if (do_relu) { v0 = fmaxf(v0, 0.f); v1 = fmaxf(v1, 0.f);
                           v2 = fmaxf(v2, 0.f); v3 = fmaxf(v3, 0.f); }
            if (do_round) { v0 = roundtf(v0); v1 = roundtf(v1);
                            v2 = roundtf(v2); v3 = roundtf(v3); }
            if (r0 < M) *(float2*)(Cout + (size_t)r0 * Nc + col) = make_float2(v0, v1);
            if (r1 < M) *(float2*)(Cout + (size_t)r1 * Nc + col) = make_float2(v2, v3);
        }
    }
}

// ---------------- fused recurrent step: Z = A@Whh^T, gates in epilogue -------
// Whh gate-interleaved (row 4c+g). P gate-interleaved, bI combined interleaved
// bias. Block covers 128 cols = 32 channels; writes h slice + c slice.
__global__ __launch_bounds__(256, 2) void fused_step_kernel(
    const float* __restrict__ A, const float* __restrict__ W,
    const float* __restrict__ P, const float* __restrict__ bI,
    const int* __restrict__ src, int t,
    float* __restrict__ c_st, float* __restrict__ h_out,
    int M, int fourH, int K1)
{
    extern __shared__ __align__(16) float sm[];
    const int tid = threadIdx.x, wid = tid >> 5, lane = tid & 31;
    const int grp = lane >> 2, tig = lane & 3;
    const int warpM = wid >> 1, warpN = wid & 1;
    const int rowBase = blockIdx.x * BM, colBase = blockIdx.y * BN;
    const int nk = K1 / BKT;
    const int cr = tid >> 3, ck = (tid & 7) * 4;

    float c[2][8][4];
#pragma unroll
    for (int mt = 0; mt < 2; ++mt)
#pragma unroll
        for (int nt = 0; nt < 8; ++nt)
#pragma unroll
            for (int i = 0; i < 4; ++i) c[mt][nt][i] = 0.f;

    auto issue = [&](int it, int s) {
        if (it < nk) {
            int kb = it * BKT;
            float* smA = sm + s * SW;
            float* smB = smA + AW;
#pragma unroll
            for (int p = 0; p < 4; ++p) {
                int r = cr + p * 32;
                int row = rowBase + r;
                int rc = (row < M) ? row : 0;
                uint32_t dst = (uint32_t)__cvta_generic_to_shared(smA + r * ASTR + ck);
                const float* g = A + (size_t)rc * K1 + kb + ck;
                int sz = (row < M) ? 16 : 0;
                asm volatile("cp.async.cg.shared.global [%0], [%1], 16, %2;\n"
                             :: "r"(dst), "l"(g), "r"(sz));
            }
#pragma unroll
            for (int p = 0; p < 4; ++p) {
                int r = cr + p * 32;
                uint32_t dst = (uint32_t)__cvta_generic_to_shared(smB + r * ASTR + ck);
                const float* g = W + (size_t)(colBase + r) * K1 + kb + ck;
                asm volatile("cp.async.cg.shared.global [%0], [%1], 16;\n"
                             :: "r"(dst), "l"(g));
            }
        }
        asm volatile("cp.async.commit_group;\n");
    };

    issue(0, 0);
    issue(1, 1);

    for (int it = 0; it < nk; ++it) {
        asm volatile("cp.async.wait_group 1;\n");
        __syncthreads();
        const int s = it % 3;
        const float* smA = sm + s * SW;
        const float* smB = smA + AW;
        const int m0 = warpM * 32, n0 = warpN * 64;
#pragma unroll
        for (int kt = 0; kt < 4; ++kt) {
            const int k0 = kt * 8;
            uint32_t af[2][4], bf[8][2];
#pragma unroll
            for (int mt = 0; mt < 2; ++mt) {
                int m = m0 + mt * 16;
                af[mt][0] = __float_as_uint(smA[(m + grp) * ASTR + k0 + tig]);
                af[mt][1] = __float_as_uint(smA[(m + 8 + grp) * ASTR + k0 + tig]);
                af[mt][2] = __float_as_uint(smA[(m + grp) * ASTR + k0 + tig + 4]);
                af[mt][3] = __float_as_uint(smA[(m + 8 + grp) * ASTR + k0 + tig + 4]);
            }
#pragma unroll
            for (int nt = 0; nt < 8; ++nt) {
                int n = n0 + nt * 8;
                bf[nt][0] = __float_as_uint(smB[(n + grp) * ASTR + k0 + tig]);
                bf[nt][1] = __float_as_uint(smB[(n + grp) * ASTR + k0 + tig + 4]);
            }
#pragma unroll
            for (int mt = 0; mt < 2; ++mt)
#pragma unroll
                for (int nt = 0; nt < 8; ++nt) {
                    asm volatile(
                        "mma.sync.aligned.m16n8k8.row.col.f32.tf32.tf32.f32 "
                        "{%0,%1,%2,%3}, {%4,%5,%6,%7}, {%8,%9}, {%0,%1,%2,%3};\n"
                        : "+f"(c[mt][nt][0]), "+f"(c[mt][nt][1]),
                          "+f"(c[mt][nt][2]), "+f"(c[mt][nt][3])
                        : "r"(af[mt][0]), "r"(af[mt][1]), "r"(af[mt][2]), "r"(af[mt][3]),
                          "r"(bf[nt][0]), "r"(bf[nt][1]));
                }
        }
        issue(it + 2, (it + 2) % 3);
    }

    // ---- epilogue: stage Z in smem, apply gates, write h/c slices ----------
    asm volatile("cp.async.wait_group 0;\n");
    __syncthreads();
    float* Zs = sm;                          // 128x128 floats (reuse pipeline)
#pragma unroll
    for (int mt = 0; mt < 2; ++mt)
#pragma unroll
        for (int nt = 0; nt < 8; ++nt) {
            int col = warpN * 64 + nt * 8 + tig * 2;
            int r0 = warpM * 32 + mt * 16 + grp;
            *(float2*)&Zs[r0 * BN + col]       = make_float2(c[mt][nt][0], c[mt][nt][1]);
            *(float2*)&Zs[(r0 + 8) * BN + col] = make_float2(c[mt][nt][2], c[mt][nt][3]);
        }
    __syncthreads();

    const int H = fourH >> 2;
    const int chanBase = blockIdx.y * 32;
#pragma unroll
    for (int i = 0; i < 16; ++i) {
        int idx = tid + i * 256;
        int r = idx >> 5, cl = idx & 31;
        int n = rowBase + r;
        if (n >= M) continue;
        int pn = src ? src[n * KK + t] : n;
        float4 zz = *(const float4*)&Zs[r * BN + 4 * cl];
        float4 pp = *(const float4*)(P + (size_t)pn * fourH + colBase + 4 * cl);
        float4 bb = *(const float4*)(bI + colBase + 4 * cl);
        float zi = zz.x + pp.x + bb.x;
        float zf = zz.y + pp.y + bb.y;
        float zg = zz.z + pp.z + bb.z;
        float zo = zz.w + pp.w + bb.w;
        float ig = sigmoidf_(zi), fg = sigmoidf_(zf);
        float gg = tanhf(zg), og = sigmoidf_(zo);
        size_t ci = (size_t)n * H + chanBase + cl;
        float cn = fg * c_st[ci] + ig * gg;
        c_st[ci] = cn;
        h_out[ci] = roundtf(og * tanhf(cn));
    }
}

// ---------------- first-step gates (interleaved P, h0=c0=0) ------------------
__global__ void gates_first_kernel(
    const float* __restrict__ P, const float* __restrict__ bI,
    const int* __restrict__ src, int t,
    float* __restrict__ c_st, float* __restrict__ h_out, int H)
{
    int idx = blockIdx.x * blockDim.x + threadIdx.x;
    if (idx >= NN * H) return;
    int n = idx / H, cl = idx - n * H;
    int pn = src ? src[n * KK + t] : n;
    float4 z = *(const float4*)(P + (size_t)pn * 4 * H + 4 * cl);
    float4 b = *(const float4*)(bI + 4 * cl);
    float ig = sigmoidf_(z.x + b.x), fg = sigmoidf_(z.y + b.y);
    float gg = tanhf(z.z + b.z),     og = sigmoidf_(z.w + b.w);
    float cn = ig * gg;              // c0 = 0
    (void)fg;
    c_st[idx] = cn;
    h_out[idx] = roundtf(og * tanhf(cn));
}

// ---------------- JK attention scores + softmax ------------------------------
__global__ void jk_score_kernel(const float* __restrict__ attw,
                                const float* __restrict__ attb,
                                float* __restrict__ wout)
{
    int gtid = blockIdx.x * blockDim.x + threadIdx.x;
    int node = gtid >> 5;
    int lane = gtid & 31;
    if (node >= NN) return;
    float sc[3];
#pragma unroll
    for (int t = 0; t < 3; ++t) {
        const float* f = d_fwd  + (size_t)t * NN * JKH + (size_t)node * JKH;
        const float* b = d_bwdp + (size_t)t * NN * JKH + (size_t)node * JKH;
        float s = 0.f;
        for (int k = lane; k < JKH; k += 32)
            s += f[k] * attw[k] + b[k] * attw[JKH + k];
#pragma unroll
        for (int off = 16; off > 0; off >>= 1)
            s += __shfl_xor_sync(0xffffffffu, s, off);
        sc[t] = s + attb[0];
    }
    if (lane == 0) {
        float m = fmaxf(sc[0], fmaxf(sc[1], sc[2]));
        float e0 = expf(sc[0] - m), e1 = expf(sc[1] - m), e2 = expf(sc[2] - m);
        float inv = 1.f / (e0 + e1 + e2);
        wout[node * 3 + 0] = e0 * inv;
        wout[node * 3 + 1] = e1 * inv;
        wout[node * 3 + 2] = e2 * inv;
    }
}

__global__ void jk_combine_kernel(float* __restrict__ out) {
    int idx = blockIdx.x * blockDim.x + threadIdx.x;
    if (idx >= NN * CC) return;
    int n = idx >> 7;
    float w0 = d_w[n * 3 + 0], w1 = d_w[n * 3 + 1], w2 = d_w[n * 3 + 2];
    out[idx] = w0 * d_xcat[idx] + w1 * d_xcat[NN * CC + idx] + w2 * d_xcat[2 * NN * CC + idx];
}

// ---------------------------------------------------------------------------
static inline int cdiv(int a, int b) { return (a + b - 1) / b; }

extern "C" void kernel_launch(void* const* d_in, const int* in_sizes, int n_in,
                              void* d_out, int out_size)
{
    const void* ei = nullptr;
    const float* x = nullptr;
    const float* wp[23];
    int wcount = 0;
    for (int i = 0; i < n_in; ++i) {
        if (in_sizes[i] == 2 * EE)       ei = d_in[i];
        else if (in_sizes[i] == NN * CC) x  = (const float*)d_in[i];
        else if (wcount < 23)            wp[wcount++] = (const float*)d_in[i];
    }
    const float *Wl1 = wp[0],  *bl1 = wp[1],  *Wr1 = wp[2];
    const float *Wl2 = wp[3],  *bl2 = wp[4],  *Wr2 = wp[5];
    const float *Wl3 = wp[6],  *bl3 = wp[7],  *Wr3 = wp[8];
    const float *Wih_a = wp[9],  *Whh_a = wp[10], *bih_a = wp[11], *bhh_a = wp[12];
    const float *Wih_f = wp[13], *Whh_f = wp[14], *bih_f = wp[15], *bhh_f = wp[16];
    const float *Wih_b = wp[17], *Whh_b = wp[18], *bih_b = wp[19], *bhh_b = wp[20];
    const float *att_w = wp[21], *att_b = wp[22];

    float *xr, *agg, *xcat, *hA, *hB, *cA, *Pa, *Pf, *Pb, *fwd, *bwdp, *cF, *cB, *wbuf, *wr;
    int* srcp;
    cudaGetSymbolAddress((void**)&srcp, d_src);
    cudaGetSymbolAddress((void**)&xr,   d_xr);
    cudaGetSymbolAddress((void**)&agg,  d_agg);
    cudaGetSymbolAddress((void**)&xcat, d_xcat);
    cudaGetSymbolAddress((void**)&hA,   d_hA);
    cudaGetSymbolAddress((void**)&hB,   d_hB);
    cudaGetSymbolAddress((void**)&cA,   d_cA);
    cudaGetSymbolAddress((void**)&Pa,   d_Pa);
    cudaGetSymbolAddress((void**)&Pf,   d_Pf);
    cudaGetSymbolAddress((void**)&Pb,   d_Pb);
    cudaGetSymbolAddress((void**)&fwd,  d_fwd);
    cudaGetSymbolAddress((void**)&bwdp, d_bwdp);
    cudaGetSymbolAddress((void**)&cF,   d_cF);
    cudaGetSymbolAddress((void**)&cB,   d_cB);
    cudaGetSymbolAddress((void**)&wbuf, d_w);
    cudaGetSymbolAddress((void**)&wr,   d_wr);

    // arena layout (floats)
    float* rWl1   = wr;            // 16384
    float* rWr1   = wr + 16384;
    float* rWl2   = wr + 32768;
    float* rWr2   = wr + 49152;
    float* rWl3   = wr + 65536;
    float* rWr3   = wr + 81920;
    float* rWih_a = wr + 98304;    // 65536, interleaved
    float* rWhh_a = wr + 163840;   // 65536, interleaved
    float* rWih_f = wr + 229376;   // 98304, interleaved
    float* rWhh_f = wr + 327680;   // 147456, interleaved
    float* rWih_b = wr + 475136;   // 98304, interleaved
    float* rWhh_b = wr + 573440;   // 147456, interleaved
    float* bIa    = wr + 720896;   // 512
    float* bIf    = wr + 721408;   // 768
    float* bIb    = wr + 722176;   // 768

    float* h1 = xcat;
    float* h2 = xcat + NN * CC;
    float* h3 = xcat + 2 * NN * CC;
    float* out = (float*)d_out;

    cudaFuncSetAttribute(tf32_gemm_kernel,
                         cudaFuncAttributeMaxDynamicSharedMemorySize, SMEM_BYTES);
    cudaFuncSetAttribute(fused_step_kernel,
                         cudaFuncAttributeMaxDynamicSharedMemorySize, SMEM_BYTES);

    const int NC_BLK = cdiv(NN * CC, 256);
    dim3 g128(cdiv(NN, BM), 1);
    dim3 g512(cdiv(NN, BM), 4);
    dim3 g768x3(cdiv(3 * NN, BM), 6);
    dim3 gf512(cdiv(NN, BM), 4);
    dim3 gf768(cdiv(NN, BM), 6);

    // ---- prep
    detect_idx_kernel<<<1, 32>>>(ei);
    convert_src_kernel<<<cdiv(EE, 256), 256>>>(ei);
    round_kernel<<<cdiv(NN * CC / 4, 256), 256>>>(x, xr, NN * CC / 4);
    round_kernel<<<16, 256>>>(Wl1, rWl1, 4096);
    round_kernel<<<16, 256>>>(Wr1, rWr1, 4096);
    round_kernel<<<16, 256>>>(Wl2, rWl2, 4096);
    round_kernel<<<16, 256>>>(Wr2, rWr2, 4096);
    round_kernel<<<16, 256>>>(Wl3, rWl3, 4096);
    round_kernel<<<16, 256>>>(Wr3, rWr3, 4096);
    permute_round_kernel<<<64, 256>>>(Wih_a, rWih_a, 128, 32);
    permute_round_kernel<<<64, 256>>>(Whh_a, rWhh_a, 128, 32);
    permute_round_kernel<<<96, 256>>>(Wih_f, rWih_f, 192, 32);
    permute_round_kernel<<<144, 256>>>(Whh_f, rWhh_f, 192, 48);
    permute_round_kernel<<<96, 256>>>(Wih_b, rWih_b, 192, 32);
    permute_round_kernel<<<144, 256>>>(Whh_b, rWhh_b, 192, 48);
    bias_comb_kernel<<<2, 256>>>(bih_a, bhh_a, bIa, 128);
    bias_comb_kernel<<<3, 256>>>(bih_f, bhh_f, bIf, 192);
    bias_comb_kernel<<<3, 256>>>(bih_b, bhh_b, bIb, 192);

    // ---- layer 1: mean SAGE + relu
    agg_mean_kernel<<<NC_BLK, 256>>>(xr, agg);
    tf32_gemm_kernel<<<g128, 256, SMEM_BYTES>>>(agg, xr, rWl1, rWr1, bl1, h1,
                                                NN, 128, 128, 128, 3);

    // ---- layer 2: max SAGE + relu
    agg_max_kernel<<<NC_BLK, 256>>>(h1, agg);
    tf32_gemm_kernel<<<g128, 256, SMEM_BYTES>>>(agg, h1, rWl2, rWr2, bl2, h2,
                                                NN, 128, 128, 128, 3);

    // ---- layer 3: LSTM aggregation; Pa interleaved, gates fused
    tf32_gemm_kernel<<<g512, 256, SMEM_BYTES>>>(h2, nullptr, rWih_a, nullptr, nullptr, Pa,
                                                NN, 512, 128, 0, 0);
    gates_first_kernel<<<NC_BLK, 256>>>(Pa, bIa, srcp, 0, cA, hA, 128);
    float* hcur = hA;
    float* hnxt = hB;
    for (int t = 1; t < KK; ++t) {
        fused_step_kernel<<<gf512, 256, SMEM_BYTES>>>(hcur, rWhh_a, Pa, bIa, srcp, t,
                                                      cA, hnxt, NN, 512, 128);
        float* tmp = hcur; hcur = hnxt; hnxt = tmp;
    }
    tf32_gemm_kernel<<<g128, 256, SMEM_BYTES>>>(hcur, h2, rWl3, rWr3, bl3, h3,
                                                NN, 128, 128, 128, 2);

    // ---- JK bi-LSTM: interleaved input projections over xcat
    tf32_gemm_kernel<<<g768x3, 256, SMEM_BYTES>>>(xcat, nullptr, rWih_f, nullptr, nullptr, Pf,
                                                  3 * NN, 768, 128, 0, 0);
    tf32_gemm_kernel<<<g768x3, 256, SMEM_BYTES>>>(xcat, nullptr, rWih_b, nullptr, nullptr, Pb,
                                                  3 * NN, 768, 128, 0, 0);

    // forward t=0 consumes xs[0]; backward t=0 consumes xs[2]
    gates_first_kernel<<<cdiv(NN * JKH, 256), 256>>>(Pf, bIf, nullptr, 0, cF, fwd, JKH);
    gates_first_kernel<<<cdiv(NN * JKH, 256), 256>>>(Pb + (size_t)2 * NN * 768, bIb,
                                                     nullptr, 0, cB,
                                                     bwdp + (size_t)2 * NN * JKH, JKH);
    for (int t = 1; t < 3; ++t) {
        fused_step_kernel<<<gf768, 256, SMEM_BYTES>>>(
            fwd + (size_t)(t - 1) * NN * JKH, rWhh_f,
            Pf + (size_t)t * NN * 768, bIf, nullptr, 0,
            cF, fwd + (size_t)t * NN * JKH, NN, 768, 192);
        fused_step_kernel<<<gf768, 256, SMEM_BYTES>>>(
            bwdp + (size_t)(3 - t) * NN * JKH, rWhh_b,
            Pb + (size_t)(2 - t) * NN * 768, bIb, nullptr, 0,
            cB, bwdp + (size_t)(2 - t) * NN * JKH, NN, 768, 192);
    }

    // ---- attention + combine
    jk_score_kernel<<<cdiv(NN * 32, 256), 256>>>(att_w, att_b, wbuf);
    jk_combine_kernel<<<NC_BLK, 256>>>(out);

    (void)out_size;
}

// round 6
// speedup vs baseline: 1.3815x; 1.3815x over previous
#include <cuda_runtime.h>
#include <math.h>
#include <stdint.h>

// ---------------------------------------------------------------------------
// GraphSAGE (mean -> max -> lstm aggr -> JK bi-LSTM), N=50000, K=16, C=128.
// Round 6: revert to round-4 structure (separate Z + gates kernels) and add a
// wide-tile GEMM (BM128 x BN256, warp 64x64) for all 512/768-col GEMMs.
// ---------------------------------------------------------------------------

#define NN 50000
#define KK 16
#define EE (NN * KK)
#define CC 128
#define JKH 192

#define BM 128
#define BN 128
#define BKT 32
#define ASTR 36
#define AW (BM * ASTR)
#define BW (BN * ASTR)
#define SW (AW + BW)
#define SMEM_BYTES (3 * SW * 4)      // 110592

#define BN2 256
#define BW2 (BN2 * ASTR)
#define SW2 (AW + BW2)
#define SMEM2_BYTES (3 * SW2 * 4)    // 165888

// ---------------- static device scratch -------------------------------------
__device__ int   d_src[EE];
__device__ int   d_is64;
__device__ float d_xr[NN * CC];
__device__ float d_agg[NN * CC];
__device__ float d_xcat[3 * NN * CC];           // h1 | h2 | h3
__device__ float d_hA[NN * CC];
__device__ float d_cA[NN * CC];
__device__ float d_Pa[NN * 512];
__device__ float d_Pf[3 * NN * 768];
__device__ float d_Pb[3 * NN * 768];
__device__ float d_Z[NN * 768];
__device__ float d_fwd[3 * NN * JKH];
__device__ float d_bwdp[3 * NN * JKH];
__device__ float d_cF[NN * JKH];
__device__ float d_cB[NN * JKH];
__device__ float d_w[NN * 3];
__device__ float d_wr[720896];

__device__ __forceinline__ float sigmoidf_(float x) { return 1.f / (1.f + expf(-x)); }

__device__ __forceinline__ uint32_t f2tf32(float f) {
    uint32_t u;
    asm("cvt.rna.tf32.f32 %0, %1;" : "=r"(u) : "f"(f));
    return u;
}
__device__ __forceinline__ float roundtf(float f) { return __uint_as_float(f2tf32(f)); }

// ---------------- edge-index probe + convert ---------------------------------
__global__ void detect_idx_kernel(const void* ei) {
    const long long* p = (const long long*)ei;
    int lane = threadIdx.x;
    int ok = 1;
#pragma unroll
    for (int i = 0; i < 4; ++i) {
        long long v = p[lane * 4 + i];
        if (v < 0 || v >= NN) ok = 0;
    }
    unsigned m = __ballot_sync(0xffffffffu, ok);
    if (lane == 0) d_is64 = (m == 0xffffffffu) ? 1 : 0;
}

__global__ void convert_src_kernel(const void* ei) {
    int idx = blockIdx.x * blockDim.x + threadIdx.x;
    if (idx >= EE) return;
    if (d_is64) d_src[idx] = (int)((const long long*)ei)[idx];
    else        d_src[idx] = ((const int*)ei)[idx];
}

// ---------------- tf32 rounding pass -----------------------------------------
__global__ void round_kernel(const float* __restrict__ in, float* __restrict__ out, int n4) {
    int i = blockIdx.x * blockDim.x + threadIdx.x;
    if (i >= n4) return;
    float4 v = ((const float4*)in)[i];
    v.x = roundtf(v.x); v.y = roundtf(v.y); v.z = roundtf(v.z); v.w = roundtf(v.w);
    ((float4*)out)[i] = v;
}

// ---------------- neighbor aggregations --------------------------------------
__global__ void agg_mean_kernel(const float* __restrict__ X, float* __restrict__ out) {
    int idx = blockIdx.x * blockDim.x + threadIdx.x;
    if (idx >= NN * CC) return;
    int n = idx >> 7, c = idx & 127;
    const int* s = d_src + n * KK;
    float acc = 0.f;
#pragma unroll
    for (int j = 0; j < KK; ++j) acc += X[(size_t)s[j] * CC + c];
    out[idx] = roundtf(acc * (1.f / 16.f));
}

__global__ void agg_max_kernel(const float* __restrict__ X, float* __restrict__ out) {
    int idx = blockIdx.x * blockDim.x + threadIdx.x;
    if (idx >= NN * CC) return;
    int n = idx >> 7, c = idx & 127;
    const int* s = d_src + n * KK;
    float acc = -INFINITY;
#pragma unroll
    for (int j = 0; j < KK; ++j) acc = fmaxf(acc, X[(size_t)s[j] * CC + c]);
    out[idx] = roundtf(acc);
}

// ---------------- tf32 GEMM 128x128 (dual-input concat) ----------------------
__global__ __launch_bounds__(256, 2) void tf32_gemm_kernel(
    const float* __restrict__ A, const float* __restrict__ B2,
    const float* __restrict__ W1, const float* __restrict__ W2,
    const float* __restrict__ bias, float* __restrict__ Cout,
    int M, int Nc, int K1, int K2, int flags)
{
    extern __shared__ __align__(16) float sm[];
    const int tid = threadIdx.x, wid = tid >> 5, lane = tid & 31;
    const int grp = lane >> 2, tig = lane & 3;
    const int warpM = wid >> 1, warpN = wid & 1;
    const int rowBase = blockIdx.x * BM, colBase = blockIdx.y * BN;
    const int Ktot = K1 + K2, nk = Ktot / BKT;
    const int cr = tid >> 3, ck = (tid & 7) * 4;

    float c[2][8][4];
#pragma unroll
    for (int mt = 0; mt < 2; ++mt)
#pragma unroll
        for (int nt = 0; nt < 8; ++nt)
#pragma unroll
            for (int i = 0; i < 4; ++i) c[mt][nt][i] = 0.f;

    auto issue = [&](int it, int s) {
        if (it < nk) {
            int kk = it * BKT;
            const float* asrc; const float* wsrc; int ld, kb;
            if (kk < K1) { asrc = A;  wsrc = W1; ld = K1; kb = kk; }
            else         { asrc = B2; wsrc = W2; ld = K2; kb = kk - K1; }
            float* smA = sm + s * SW;
            float* smB = smA + AW;
#pragma unroll
            for (int p = 0; p < 4; ++p) {
                int r = cr + p * 32;
                int row = rowBase + r;
                int rc = (row < M) ? row : 0;
                uint32_t dst = (uint32_t)__cvta_generic_to_shared(smA + r * ASTR + ck);
                const float* g = asrc + (size_t)rc * ld + kb + ck;
                int sz = (row < M) ? 16 : 0;
                asm volatile("cp.async.cg.shared.global [%0], [%1], 16, %2;\n"
                             :: "r"(dst), "l"(g), "r"(sz));
            }
#pragma unroll
            for (int p = 0; p < 4; ++p) {
                int r = cr + p * 32;
                uint32_t dst = (uint32_t)__cvta_generic_to_shared(smB + r * ASTR + ck);
                const float* g = wsrc + (size_t)(colBase + r) * ld + kb + ck;
                asm volatile("cp.async.cg.shared.global [%0], [%1], 16;\n"
                             :: "r"(dst), "l"(g));
            }
        }
        asm volatile("cp.async.commit_group;\n");
    };

    issue(0, 0);
    issue(1, 1);

    for (int it = 0; it < nk; ++it) {
        asm volatile("cp.async.wait_group 1;\n");
        __syncthreads();
        const int s = it % 3;
        const float* smA = sm + s * SW;
        const float* smB = smA + AW;
        const int m0 = warpM * 32, n0 = warpN * 64;
#pragma unroll
        for (int kt = 0; kt < 4; ++kt) {
            const int k0 = kt * 8;
            uint32_t af[2][4], bf[8][2];
#pragma unroll
            for (int mt = 0; mt < 2; ++mt) {
                int m = m0 + mt * 16;
                af[mt][0] = __float_as_uint(smA[(m + grp) * ASTR + k0 + tig]);
                af[mt][1] = __float_as_uint(smA[(m + 8 + grp) * ASTR + k0 + tig]);
                af[mt][2] = __float_as_uint(smA[(m + grp) * ASTR + k0 + tig + 4]);
                af[mt][3] = __float_as_uint(smA[(m + 8 + grp) * ASTR + k0 + tig + 4]);
            }
#pragma unroll
            for (int nt = 0; nt < 8; ++nt) {
                int n = n0 + nt * 8;
                bf[nt][0] = __float_as_uint(smB[(n + grp) * ASTR + k0 + tig]);
                bf[nt][1] = __float_as_uint(smB[(n + grp) * ASTR + k0 + tig + 4]);
            }
#pragma unroll
            for (int mt = 0; mt < 2; ++mt)
#pragma unroll
                for (int nt = 0; nt < 8; ++nt) {
                    asm volatile(
                        "mma.sync.aligned.m16n8k8.row.col.f32.tf32.tf32.f32 "
                        "{%0,%1,%2,%3}, {%4,%5,%6,%7}, {%8,%9}, {%0,%1,%2,%3};\n"
                        : "+f"(c[mt][nt][0]), "+f"(c[mt][nt][1]),
                          "+f"(c[mt][nt][2]), "+f"(c[mt][nt][3])
                        : "r"(af[mt][0]), "r"(af[mt][1]), "r"(af[mt][2]), "r"(af[mt][3]),
                          "r"(bf[nt][0]), "r"(bf[nt][1]));
                }
        }
        issue(it + 2, (it + 2) % 3);
    }

    const int do_relu = flags & 1, do_round = flags & 2;
#pragma unroll
    for (int mt = 0; mt < 2; ++mt) {
#pragma unroll
        for (int nt = 0; nt < 8; ++nt) {
            int col = colBase + warpN * 64 + nt * 8 + tig * 2;
            float b0 = bias ? bias[col] : 0.f;
            float b1 = bias ? bias[col + 1] : 0.f;
            int r0 = rowBase + warpM * 32 + mt * 16 + grp;
            int r1 = r0 + 8;
            float v0 = c[mt][nt][0] + b0, v1 = c[mt][nt][1] + b1;
            float v2 = c[mt][nt][2] + b0, v3 = c[mt][nt][3] + b1;
            if (do_relu) { v0 = fmaxf(v0, 0.f); v1 = fmaxf(v1, 0.f);
                           v2 = fmaxf(v2, 0.f); v3 = fmaxf(v3, 0.f); }
            if (do_round) { v0 = roundtf(v0); v1 = roundtf(v1);
                            v2 = roundtf(v2); v3 = roundtf(v3); }
            if (r0 < M) *(float2*)(Cout + (size_t)r0 * Nc + col) = make_float2(v0, v1);
            if (r1 < M) *(float2*)(Cout + (size_t)r1 * Nc + col) = make_float2(v2, v3);
        }
    }
}

// ---------------- tf32 GEMM 128x256, warp tile 64x64 (single input) ----------
// Cout = A@W^T ; Nc % 256 == 0; no bias/act (wide GEMMs never need them).
__global__ __launch_bounds__(256, 1) void tf32_gemm_wide_kernel(
    const float* __restrict__ A, const float* __restrict__ W,
    float* __restrict__ Cout, int M, int Nc, int K1)
{
    extern __shared__ __align__(16) float sm[];
    const int tid = threadIdx.x, wid = tid >> 5, lane = tid & 31;
    const int grp = lane >> 2, tig = lane & 3;
    const int warpM = wid >> 2;          // 0..1, 64 rows each
    const int warpN = wid & 3;           // 0..3, 64 cols each
    const int rowBase = blockIdx.x * BM, colBase = blockIdx.y * BN2;
    const int nk = K1 / BKT;
    const int cr = tid >> 3, ck = (tid & 7) * 4;

    float c[4][8][4];
#pragma unroll
    for (int mt = 0; mt < 4; ++mt)
#pragma unroll
        for (int nt = 0; nt < 8; ++nt)
#pragma unroll
            for (int i = 0; i < 4; ++i) c[mt][nt][i] = 0.f;

    auto issue = [&](int it, int s) {
        if (it < nk) {
            int kb = it * BKT;
            float* smA = sm + s * SW2;
            float* smB = smA + AW;
#pragma unroll
            for (int p = 0; p < 4; ++p) {
                int r = cr + p * 32;
                int row = rowBase + r;
                int rc = (row < M) ? row : 0;
                uint32_t dst = (uint32_t)__cvta_generic_to_shared(smA + r * ASTR + ck);
                const float* g = A + (size_t)rc * K1 + kb + ck;
                int sz = (row < M) ? 16 : 0;
                asm volatile("cp.async.cg.shared.global [%0], [%1], 16, %2;\n"
                             :: "r"(dst), "l"(g), "r"(sz));
            }
#pragma unroll
            for (int p = 0; p < 8; ++p) {
                int r = cr + p * 32;
                uint32_t dst = (uint32_t)__cvta_generic_to_shared(smB + r * ASTR + ck);
                const float* g = W + (size_t)(colBase + r) * K1 + kb + ck;
                asm volatile("cp.async.cg.shared.global [%0], [%1], 16;\n"
                             :: "r"(dst), "l"(g));
            }
        }
        asm volatile("cp.async.commit_group;\n");
    };

    issue(0, 0);
    issue(1, 1);

    for (int it = 0; it < nk; ++it) {
        asm volatile("cp.async.wait_group 1;\n");
        __syncthreads();
        const int s = it % 3;
        const float* smA = sm + s * SW2;
        const float* smB = smA + AW;
        const int m0 = warpM * 64, n0 = warpN * 64;
#pragma unroll
        for (int kt = 0; kt < 4; ++kt) {
            const int k0 = kt * 8;
            uint32_t af[4][4], bf[8][2];
#pragma unroll
            for (int mt = 0; mt < 4; ++mt) {
                int m = m0 + mt * 16;
                af[mt][0] = __float_as_uint(smA[(m + grp) * ASTR + k0 + tig]);
                af[mt][1] = __float_as_uint(smA[(m + 8 + grp) * ASTR + k0 + tig]);
                af[mt][2] = __float_as_uint(smA[(m + grp) * ASTR + k0 + tig + 4]);
                af[mt][3] = __float_as_uint(smA[(m + 8 + grp) * ASTR + k0 + tig + 4]);
            }
#pragma unroll
            for (int nt = 0; nt < 8; ++nt) {
                int n = n0 + nt * 8;
                bf[nt][0] = __float_as_uint(smB[(n + grp) * ASTR + k0 + tig]);
                bf[nt][1] = __float_as_uint(smB[(n + grp) * ASTR + k0 + tig + 4]);
            }
#pragma unroll
            for (int mt = 0; mt < 4; ++mt)
#pragma unroll
                for (int nt = 0; nt < 8; ++nt) {
                    asm volatile(
                        "mma.sync.aligned.m16n8k8.row.col.f32.tf32.tf32.f32 "
                        "{%0,%1,%2,%3}, {%4,%5,%6,%7}, {%8,%9}, {%0,%1,%2,%3};\n"
                        : "+f"(c[mt][nt][0]), "+f"(c[mt][nt][1]),
                          "+f"(c[mt][nt][2]), "+f"(c[mt][nt][3])
                        : "r"(af[mt][0]), "r"(af[mt][1]), "r"(af[mt][2]), "r"(af[mt][3]),
                          "r"(bf[nt][0]), "r"(bf[nt][1]));
                }
        }
        issue(it + 2, (it + 2) % 3);
    }

#pragma unroll
    for (int mt = 0; mt < 4; ++mt) {
#pragma unroll
        for (int nt = 0; nt < 8; ++nt) {
            int col = colBase + warpN * 64 + nt * 8 + tig * 2;
            int r0 = rowBase + warpM * 64 + mt * 16 + grp;
            int r1 = r0 + 8;
            if (r0 < M) *(float2*)(Cout + (size_t)r0 * Nc + col) =
                make_float2(c[mt][nt][0], c[mt][nt][1]);
            if (r1 < M) *(float2*)(Cout + (size_t)r1 * Nc + col) =
                make_float2(c[mt][nt][2], c[mt][nt][3]);
        }
    }
}

// ---------------- LSTM gates (float4): z = Zrec + P[gathered] + biases -------
__global__ void lstm_gates_kernel(
    const float* __restrict__ Zrec,
    const float* __restrict__ P,
    const int* __restrict__ src, int t,
    const float* __restrict__ bih, const float* __restrict__ bhh,
    float* __restrict__ h_out, float* __restrict__ c_st,
    int H, int first)
{
    int hv = H >> 2;
    int idx = blockIdx.x * blockDim.x + threadIdx.x;
    if (idx >= NN * hv) return;
    int n = idx / hv, q = idx - n * hv;
    int pn = src ? src[n * KK + t] : n;
    const float4* pr = (const float4*)(P + (size_t)pn * 4 * H);
    const float4* zr = Zrec ? (const float4*)(Zrec + (size_t)n * 4 * H) : nullptr;
    const float4* b1 = (const float4*)bih;
    const float4* b2 = (const float4*)bhh;

    float4 z[4];
#pragma unroll
    for (int g = 0; g < 4; ++g) {
        float4 v = pr[g * hv + q];
        float4 a = b1[g * hv + q], b = b2[g * hv + q];
        v.x += a.x + b.x; v.y += a.y + b.y; v.z += a.z + b.z; v.w += a.w + b.w;
        if (zr) {
            float4 u = zr[g * hv + q];
            v.x += u.x; v.y += u.y; v.z += u.z; v.w += u.w;
        }
        z[g] = v;
    }
    float4 cold = first ? make_float4(0.f, 0.f, 0.f, 0.f) : ((float4*)c_st)[idx];
    float4 cn, hn;
#pragma unroll
    for (int e = 0; e < 4; ++e) {
        float zi = (&z[0].x)[e], zf = (&z[1].x)[e], zg = (&z[2].x)[e], zo = (&z[3].x)[e];
        float ig = sigmoidf_(zi), fg = sigmoidf_(zf);
        float gg = tanhf(zg), og = sigmoidf_(zo);
        float cc = fg * (&cold.x)[e] + ig * gg;
        (&cn.x)[e] = cc;
        (&hn.x)[e] = roundtf(og * tanhf(cc));
    }
    ((float4*)c_st)[idx] = cn;
    ((float4*)h_out)[idx] = hn;
}

// ---------------- JK attention scores + softmax ------------------------------
__global__ void jk_score_kernel(const float* __restrict__ attw,
                                const float* __restrict__ attb,
                                float* __restrict__ wout)
{
    int gtid = blockIdx.x * blockDim.x + threadIdx.x;
    int node = gtid >> 5;
    int lane = gtid & 31;
    if (node >= NN) return;
    float sc[3];
#pragma unroll
    for (int t = 0; t < 3; ++t) {
        const float* f = d_fwd  + (size_t)t * NN * JKH + (size_t)node * JKH;
        const float* b = d_bwdp + (size_t)t * NN * JKH + (size_t)node * JKH;
        float s = 0.f;
        for (int k = lane; k < JKH; k += 32)
            s += f[k] * attw[k] + b[k] * attw[JKH + k];
#pragma unroll
        for (int off = 16; off > 0; off >>= 1)
            s += __shfl_xor_sync(0xffffffffu, s, off);
        sc[t] = s + attb[0];
    }
    if (lane == 0) {
        float m = fmaxf(sc[0], fmaxf(sc[1], sc[2]));
        float e0 = expf(sc[0] - m), e1 = expf(sc[1] - m), e2 = expf(sc[2] - m);
        float inv = 1.f / (e0 + e1 + e2);
        wout[node * 3 + 0] = e0 * inv;
        wout[node * 3 + 1] = e1 * inv;
        wout[node * 3 + 2] = e2 * inv;
    }
}

__global__ void jk_combine_kernel(float* __restrict__ out) {
    int idx = blockIdx.x * blockDim.x + threadIdx.x;
    if (idx >= NN * CC) return;
    int n = idx >> 7;
    float w0 = d_w[n * 3 + 0], w1 = d_w[n * 3 + 1], w2 = d_w[n * 3 + 2];
    out[idx] = w0 * d_xcat[idx] + w1 * d_xcat[NN * CC + idx] + w2 * d_xcat[2 * NN * CC + idx];
}

// ---------------------------------------------------------------------------
static inline int cdiv(int a, int b) { return (a + b - 1) / b; }

extern "C" void kernel_launch(void* const* d_in, const int* in_sizes, int n_in,
                              void* d_out, int out_size)
{
    const void* ei = nullptr;
    const float* x = nullptr;
    const float* wp[23];
    int wcount = 0;
    for (int i = 0; i < n_in; ++i) {
        if (in_sizes[i] == 2 * EE)       ei = d_in[i];
        else if (in_sizes[i] == NN * CC) x  = (const float*)d_in[i];
        else if (wcount < 23)            wp[wcount++] = (const float*)d_in[i];
    }
    const float *Wl1 = wp[0],  *bl1 = wp[1],  *Wr1 = wp[2];
    const float *Wl2 = wp[3],  *bl2 = wp[4],  *Wr2 = wp[5];
    const float *Wl3 = wp[6],  *bl3 = wp[7],  *Wr3 = wp[8];
    const float *Wih_a = wp[9],  *Whh_a = wp[10], *bih_a = wp[11], *bhh_a = wp[12];
    const float *Wih_f = wp[13], *Whh_f = wp[14], *bih_f = wp[15], *bhh_f = wp[16];
    const float *Wih_b = wp[17], *Whh_b = wp[18], *bih_b = wp[19], *bhh_b = wp[20];
    const float *att_w = wp[21], *att_b = wp[22];

    float *xr, *agg, *xcat, *hA, *cA, *Pa, *Pf, *Pb, *Z, *fwd, *bwdp, *cF, *cB, *wbuf, *wr;
    int* srcp;
    cudaGetSymbolAddress((void**)&srcp, d_src);
    cudaGetSymbolAddress((void**)&xr,   d_xr);
    cudaGetSymbolAddress((void**)&agg,  d_agg);
    cudaGetSymbolAddress((void**)&xcat, d_xcat);
    cudaGetSymbolAddress((void**)&hA,   d_hA);
    cudaGetSymbolAddress((void**)&cA,   d_cA);
    cudaGetSymbolAddress((void**)&Pa,   d_Pa);
    cudaGetSymbolAddress((void**)&Pf,   d_Pf);
    cudaGetSymbolAddress((void**)&Pb,   d_Pb);
    cudaGetSymbolAddress((void**)&Z,    d_Z);
    cudaGetSymbolAddress((void**)&fwd,  d_fwd);
    cudaGetSymbolAddress((void**)&bwdp, d_bwdp);
    cudaGetSymbolAddress((void**)&cF,   d_cF);
    cudaGetSymbolAddress((void**)&cB,   d_cB);
    cudaGetSymbolAddress((void**)&wbuf, d_w);
    cudaGetSymbolAddress((void**)&wr,   d_wr);

    float* rWl1 = wr;                 float* rWr1 = rWl1 + 16384;
    float* rWl2 = rWr1 + 16384;       float* rWr2 = rWl2 + 16384;
    float* rWl3 = rWr2 + 16384;       float* rWr3 = rWl3 + 16384;
    float* rWih_a = rWr3 + 16384;     float* rWhh_a = rWih_a + 65536;
    float* rWih_f = rWhh_a + 65536;   float* rWhh_f = rWih_f + 98304;
    float* rWih_b = rWhh_f + 147456;  float* rWhh_b = rWih_b + 98304;

    float* h1 = xcat;
    float* h2 = xcat + NN * CC;
    float* h3 = xcat + 2 * NN * CC;
    float* out = (float*)d_out;

    cudaFuncSetAttribute(tf32_gemm_kernel,
                         cudaFuncAttributeMaxDynamicSharedMemorySize, SMEM_BYTES);
    cudaFuncSetAttribute(tf32_gemm_wide_kernel,
                         cudaFuncAttributeMaxDynamicSharedMemorySize, SMEM2_BYTES);

    const int NC_BLK4 = cdiv(NN * CC / 4, 256);
    const int NJ_BLK4 = cdiv(NN * JKH / 4, 256);
    const int NC_BLK  = cdiv(NN * CC, 256);
    dim3 g128(cdiv(NN, BM), 1);
    dim3 gw512(cdiv(NN, BM), 2);          // wide kernel, Nc=512
    dim3 gw768(cdiv(NN, BM), 3);          // wide kernel, Nc=768
    dim3 gw768x3(cdiv(3 * NN, BM), 3);    // wide kernel, M=150000, Nc=768

    // ---- prep
    detect_idx_kernel<<<1, 32>>>(ei);
    convert_src_kernel<<<cdiv(EE, 256), 256>>>(ei);
    round_kernel<<<cdiv(NN * CC / 4, 256), 256>>>(x, xr, NN * CC / 4);
    round_kernel<<<16, 256>>>(Wl1, rWl1, 4096);
    round_kernel<<<16, 256>>>(Wr1, rWr1, 4096);
    round_kernel<<<16, 256>>>(Wl2, rWl2, 4096);
    round_kernel<<<16, 256>>>(Wr2, rWr2, 4096);
    round_kernel<<<16, 256>>>(Wl3, rWl3, 4096);
    round_kernel<<<16, 256>>>(Wr3, rWr3, 4096);
    round_kernel<<<64, 256>>>(Wih_a, rWih_a, 16384);
    round_kernel<<<64, 256>>>(Whh_a, rWhh_a, 16384);
    round_kernel<<<96, 256>>>(Wih_f, rWih_f, 24576);
    round_kernel<<<144, 256>>>(Whh_f, rWhh_f, 36864);
    round_kernel<<<96, 256>>>(Wih_b, rWih_b, 24576);
    round_kernel<<<144, 256>>>(Whh_b, rWhh_b, 36864);

    // ---- layer 1: mean SAGE + relu
    agg_mean_kernel<<<NC_BLK, 256>>>(xr, agg);
    tf32_gemm_kernel<<<g128, 256, SMEM_BYTES>>>(agg, xr, rWl1, rWr1, bl1, h1,
                                                NN, 128, 128, 128, 3);

    // ---- layer 2: max SAGE + relu
    agg_max_kernel<<<NC_BLK, 256>>>(h1, agg);
    tf32_gemm_kernel<<<g128, 256, SMEM_BYTES>>>(agg, h1, rWl2, rWr2, bl2, h2,
                                                NN, 128, 128, 128, 3);

    // ---- layer 3: LSTM aggregation (hoisted input projection)
    tf32_gemm_wide_kernel<<<gw512, 256, SMEM2_BYTES>>>(h2, rWih_a, Pa, NN, 512, 128);
    for (int t = 0; t < KK; ++t) {
        const float* zr = nullptr;
        if (t > 0) {
            tf32_gemm_wide_kernel<<<gw512, 256, SMEM2_BYTES>>>(hA, rWhh_a, Z, NN, 512, 128);
            zr = Z;
        }
        lstm_gates_kernel<<<NC_BLK4, 256>>>(zr, Pa, srcp, t, bih_a, bhh_a,
                                            hA, cA, 128, t == 0);
    }
    tf32_gemm_kernel<<<g128, 256, SMEM_BYTES>>>(hA, h2, rWl3, rWr3, bl3, h3,
                                                NN, 128, 128, 128, 2);

    // ---- JK bi-LSTM: batched input projections
    tf32_gemm_wide_kernel<<<gw768x3, 256, SMEM2_BYTES>>>(xcat, rWih_f, Pf, 3 * NN, 768, 128);
    tf32_gemm_wide_kernel<<<gw768x3, 256, SMEM2_BYTES>>>(xcat, rWih_b, Pb, 3 * NN, 768, 128);

    for (int t = 0; t < 3; ++t) {
        const float* zrF = nullptr;
        if (t > 0) {
            tf32_gemm_wide_kernel<<<gw768, 256, SMEM2_BYTES>>>(
                fwd + (size_t)(t - 1) * NN * JKH, rWhh_f, Z, NN, 768, JKH);
            zrF = Z;
        }
        lstm_gates_kernel<<<NJ_BLK4, 256>>>(zrF, Pf + (size_t)t * NN * 768, nullptr, 0,
                                            bih_f, bhh_f,
                                            fwd + (size_t)t * NN * JKH, cF, JKH, t == 0);
        const float* zrB = nullptr;
        if (t > 0) {
            tf32_gemm_wide_kernel<<<gw768, 256, SMEM2_BYTES>>>(
                bwdp + (size_t)(3 - t) * NN * JKH, rWhh_b, Z, NN, 768, JKH);
            zrB = Z;
        }
        lstm_gates_kernel<<<NJ_BLK4, 256>>>(zrB, Pb + (size_t)(2 - t) * NN * 768, nullptr, 0,
                                            bih_b, bhh_b,
                                            bwdp + (size_t)(2 - t) * NN * JKH, cB, JKH, t == 0);
    }

    // ---- attention + combine
    jk_score_kernel<<<cdiv(NN * 32, 256), 256>>>(att_w, att_b, wbuf);
    jk_combine_kernel<<<NC_BLK, 256>>>(out);

    (void)out_size;
}

// round 9
// speedup vs baseline: 1.8099x; 1.3101x over previous
#include <cuda_runtime.h>
#include <cuda_fp16.h>
#include <math.h>
#include <stdint.h>

// ---------------------------------------------------------------------------
// GraphSAGE (mean -> max -> lstm aggr -> JK bi-LSTM), N=50000, K=16, C=128.
// Round 9 (fp16 resubmit #2 + batched weight conversion): fp16 mma.m16n8k16
// (same 10-bit mantissa as tf32, 2x rate), fp32 accumulation, fp32 P/Z/c.
// ---------------------------------------------------------------------------

#define NN 50000
#define KK 16
#define EE (NN * KK)
#define CC 128
#define JKH 192

#define BM 128
#define BN 128
#define BKT 32                      // halves per K-tile
#define RSTRH 40                    // halves per smem row (32 + 8 pad) = 80 B
#define RSTRW 20                    // words per smem row
#define TILE_B (BM * RSTRH * 2)     // 10240 bytes per tile side
#define STAGE_B (2 * TILE_B)        // 20480
#define SMEM_BYTES (3 * STAGE_B)    // 61440

// ---------------- static device scratch -------------------------------------
__device__ int    d_src[EE];
__device__ int    d_is64;
__device__ __half d_xh[NN * CC];
__device__ __half d_aggh[NN * CC];
__device__ __half d_xcath[3 * NN * CC];         // h1 | h2 | h3 (fp16)
__device__ __half d_hAh[NN * CC];
__device__ float  d_cA[NN * CC];
__device__ float  d_Pa[NN * 512];
__device__ float  d_Pf[3 * NN * 768];
__device__ float  d_Pb[3 * NN * 768];
__device__ float  d_Z[NN * 768];
__device__ __half d_fwdh[3 * NN * JKH];
__device__ __half d_bwdph[3 * NN * JKH];
__device__ float  d_cF[NN * JKH];
__device__ float  d_cB[NN * JKH];
__device__ float  d_w[NN * 3];
__device__ __half d_wh[720896];                 // fp16 weights arena

__device__ __forceinline__ float sigmoidf_(float x) { return 1.f / (1.f + expf(-x)); }

// ---------------- edge-index probe + convert ---------------------------------
__global__ void detect_idx_kernel(const void* ei) {
    const long long* p = (const long long*)ei;
    int lane = threadIdx.x;
    int ok = 1;
#pragma unroll
    for (int i = 0; i < 4; ++i) {
        long long v = p[lane * 4 + i];
        if (v < 0 || v >= NN) ok = 0;
    }
    unsigned m = __ballot_sync(0xffffffffu, ok);
    if (lane == 0) d_is64 = (m == 0xffffffffu) ? 1 : 0;
}

__global__ void convert_src_kernel(const void* ei) {
    int idx = blockIdx.x * blockDim.x + threadIdx.x;
    if (idx >= EE) return;
    if (d_is64) d_src[idx] = (int)((const long long*)ei)[idx];
    else        d_src[idx] = ((const int*)ei)[idx];
}

// ---------------- fp32 -> fp16 conversion ------------------------------------
__global__ void cvt_half_kernel(const float* __restrict__ in, __half* __restrict__ out, int n4) {
    int i = blockIdx.x * blockDim.x + threadIdx.x;
    if (i >= n4) return;
    float4 v = ((const float4*)in)[i];
    ((__half2*)out)[i * 2]     = __floats2half2_rn(v.x, v.y);
    ((__half2*)out)[i * 2 + 1] = __floats2half2_rn(v.z, v.w);
}

// Batched multi-segment conversion: one launch for all 13 weight tensors.
#define NSEG 13
struct CvtJobs {
    const float* src[NSEG];
    __half*      dst[NSEG];
    int          end4[NSEG];   // cumulative float4 counts
};

__global__ void cvt_half_multi_kernel(CvtJobs jobs, int total4) {
    int i = blockIdx.x * blockDim.x + threadIdx.x;
    if (i >= total4) return;
    int seg = 0;
#pragma unroll
    for (int s = 0; s < NSEG; ++s)
        if (i >= jobs.end4[s]) seg = s + 1;
    int base = (seg == 0) ? 0 : jobs.end4[seg - 1];
    int j = i - base;
    float4 v = ((const float4*)jobs.src[seg])[j];
    ((__half2*)jobs.dst[seg])[j * 2]     = __floats2half2_rn(v.x, v.y);
    ((__half2*)jobs.dst[seg])[j * 2 + 1] = __floats2half2_rn(v.z, v.w);
}

// ---------------- neighbor aggregations (half2) ------------------------------
__global__ void agg_mean_kernel(const __half* __restrict__ X, __half* __restrict__ out) {
    int idx = blockIdx.x * blockDim.x + threadIdx.x;
    if (idx >= NN * 64) return;
    int n = idx >> 6, c2 = idx & 63;
    const int* s = d_src + n * KK;
    float ax = 0.f, ay = 0.f;
#pragma unroll
    for (int j = 0; j < KK; ++j) {
        float2 v = __half22float2(*(const __half2*)(X + (size_t)s[j] * CC + 2 * c2));
        ax += v.x; ay += v.y;
    }
    ((__half2*)out)[idx] = __floats2half2_rn(ax * (1.f / 16.f), ay * (1.f / 16.f));
}

__global__ void agg_max_kernel(const __half* __restrict__ X, __half* __restrict__ out) {
    int idx = blockIdx.x * blockDim.x + threadIdx.x;
    if (idx >= NN * 64) return;
    int n = idx >> 6, c2 = idx & 63;
    const int* s = d_src + n * KK;
    float ax = -INFINITY, ay = -INFINITY;
#pragma unroll
    for (int j = 0; j < KK; ++j) {
        float2 v = __half22float2(*(const __half2*)(X + (size_t)s[j] * CC + 2 * c2));
        ax = fmaxf(ax, v.x); ay = fmaxf(ay, v.y);
    }
    ((__half2*)out)[idx] = __floats2half2_rn(ax, ay);
}

// ---------------- fp16 GEMM (cp.async 3-stage, m16n8k16) ---------------------
// Cout = act( A[MxK1]@W1^T + B2[MxK2]@W2^T + bias ); K-concat over halves.
// Writes CoutF (fp32) if non-null else CoutH (fp16). relu: apply max(0,.)
__global__ __launch_bounds__(256, 2) void h16_gemm_kernel(
    const __half* __restrict__ A, const __half* __restrict__ B2,
    const __half* __restrict__ W1, const __half* __restrict__ W2,
    const float* __restrict__ bias,
    float* __restrict__ CoutF, __half* __restrict__ CoutH,
    int M, int Nc, int K1, int K2, int relu)
{
    extern __shared__ __align__(16) char smraw[];
    const int tid = threadIdx.x, wid = tid >> 5, lane = tid & 31;
    const int grp = lane >> 2, tig = lane & 3;
    const int warpM = wid >> 1, warpN = wid & 1;
    const int rowBase = blockIdx.x * BM, colBase = blockIdx.y * BN;
    const int Ktot = K1 + K2, nk = Ktot / BKT;
    const int cr = tid >> 2;               // row 0..63, +64 on second pass
    const int chh = (tid & 3) * 8;         // half offset within row

    float c[2][8][4];
#pragma unroll
    for (int mt = 0; mt < 2; ++mt)
#pragma unroll
        for (int nt = 0; nt < 8; ++nt)
#pragma unroll
            for (int i = 0; i < 4; ++i) c[mt][nt][i] = 0.f;

    auto issue = [&](int it, int s) {
        if (it < nk) {
            int kk = it * BKT;
            const __half* asrc; const __half* wsrc; int ld, kb;
            if (kk < K1) { asrc = A;  wsrc = W1; ld = K1; kb = kk; }
            else         { asrc = B2; wsrc = W2; ld = K2; kb = kk - K1; }
            char* smA = smraw + s * STAGE_B;
            char* smB = smA + TILE_B;
#pragma unroll
            for (int p = 0; p < 2; ++p) {
                int r = cr + p * 64;
                int row = rowBase + r;
                int rc = (row < M) ? row : 0;
                uint32_t dst = (uint32_t)__cvta_generic_to_shared(smA + r * (RSTRH * 2) + chh * 2);
                const __half* g = asrc + (size_t)rc * ld + kb + chh;
                int sz = (row < M) ? 16 : 0;
                asm volatile("cp.async.cg.shared.global [%0], [%1], 16, %2;\n"
                             :: "r"(dst), "l"(g), "r"(sz));
            }
#pragma unroll
            for (int p = 0; p < 2; ++p) {
                int r = cr + p * 64;
                uint32_t dst = (uint32_t)__cvta_generic_to_shared(smB + r * (RSTRH * 2) + chh * 2);
                const __half* g = wsrc + (size_t)(colBase + r) * ld + kb + chh;
                asm volatile("cp.async.cg.shared.global [%0], [%1], 16;\n"
                             :: "r"(dst), "l"(g));
            }
        }
        asm volatile("cp.async.commit_group;\n");
    };

    issue(0, 0);
    issue(1, 1);

    for (int it = 0; it < nk; ++it) {
        asm volatile("cp.async.wait_group 1;\n");
        __syncthreads();
        const int s = it % 3;
        const uint32_t* smA = (const uint32_t*)(smraw + s * STAGE_B);
        const uint32_t* smB = (const uint32_t*)(smraw + s * STAGE_B + TILE_B);
        const int m0 = warpM * 32, n0 = warpN * 64;
#pragma unroll
        for (int kt = 0; kt < 2; ++kt) {
            const int wk = kt * 8;
            uint32_t af[2][4], bf[8][2];
#pragma unroll
            for (int mt = 0; mt < 2; ++mt) {
                int m = m0 + mt * 16;
                af[mt][0] = smA[(m + grp) * RSTRW + wk + tig];
                af[mt][1] = smA[(m + 8 + grp) * RSTRW + wk + tig];
                af[mt][2] = smA[(m + grp) * RSTRW + wk + tig + 4];
                af[mt][3] = smA[(m + 8 + grp) * RSTRW + wk + tig + 4];
            }
#pragma unroll
            for (int nt = 0; nt < 8; ++nt) {
                int n = n0 + nt * 8;
                bf[nt][0] = smB[(n + grp) * RSTRW + wk + tig];
                bf[nt][1] = smB[(n + grp) * RSTRW + wk + tig + 4];
            }
#pragma unroll
            for (int mt = 0; mt < 2; ++mt)
#pragma unroll
                for (int nt = 0; nt < 8; ++nt) {
                    asm volatile(
                        "mma.sync.aligned.m16n8k16.row.col.f32.f16.f16.f32 "
                        "{%0,%1,%2,%3}, {%4,%5,%6,%7}, {%8,%9}, {%0,%1,%2,%3};\n"
                        : "+f"(c[mt][nt][0]), "+f"(c[mt][nt][1]),
                          "+f"(c[mt][nt][2]), "+f"(c[mt][nt][3])
                        : "r"(af[mt][0]), "r"(af[mt][1]), "r"(af[mt][2]), "r"(af[mt][3]),
                          "r"(bf[nt][0]), "r"(bf[nt][1]));
                }
        }
        issue(it + 2, (it + 2) % 3);
    }

#pragma unroll
    for (int mt = 0; mt < 2; ++mt) {
#pragma unroll
        for (int nt = 0; nt < 8; ++nt) {
            int col = colBase + warpN * 64 + nt * 8 + tig * 2;
            float b0 = bias ? bias[col] : 0.f;
            float b1 = bias ? bias[col + 1] : 0.f;
            int r0 = rowBase + warpM * 32 + mt * 16 + grp;
            int r1 = r0 + 8;
            float v0 = c[mt][nt][0] + b0, v1 = c[mt][nt][1] + b1;
            float v2 = c[mt][nt][2] + b0, v3 = c[mt][nt][3] + b1;
            if (relu) { v0 = fmaxf(v0, 0.f); v1 = fmaxf(v1, 0.f);
                        v2 = fmaxf(v2, 0.f); v3 = fmaxf(v3, 0.f); }
            if (CoutF) {
                if (r0 < M) *(float2*)(CoutF + (size_t)r0 * Nc + col) = make_float2(v0, v1);
                if (r1 < M) *(float2*)(CoutF + (size_t)r1 * Nc + col) = make_float2(v2, v3);
            } else {
                if (r0 < M) *(__half2*)(CoutH + (size_t)r0 * Nc + col) = __floats2half2_rn(v0, v1);
                if (r1 < M) *(__half2*)(CoutH + (size_t)r1 * Nc + col) = __floats2half2_rn(v2, v3);
            }
        }
    }
}

// ---------------- LSTM gates: z = Zrec + P[gathered] + biases ----------------
// P/Zrec fp32; h_out fp16; c_st fp32.
__global__ void lstm_gates_kernel(
    const float* __restrict__ Zrec,
    const float* __restrict__ P,
    const int* __restrict__ src, int t,
    const float* __restrict__ bih, const float* __restrict__ bhh,
    __half* __restrict__ h_out, float* __restrict__ c_st,
    int H, int first)
{
    int hv = H >> 2;
    int idx = blockIdx.x * blockDim.x + threadIdx.x;
    if (idx >= NN * hv) return;
    int n = idx / hv, q = idx - n * hv;
    int pn = src ? src[n * KK + t] : n;
    const float4* pr = (const float4*)(P + (size_t)pn * 4 * H);
    const float4* zr = Zrec ? (const float4*)(Zrec + (size_t)n * 4 * H) : nullptr;
    const float4* b1 = (const float4*)bih;
    const float4* b2 = (const float4*)bhh;

    float4 z[4];
#pragma unroll
    for (int g = 0; g < 4; ++g) {
        float4 v = pr[g * hv + q];
        float4 a = b1[g * hv + q], b = b2[g * hv + q];
        v.x += a.x + b.x; v.y += a.y + b.y; v.z += a.z + b.z; v.w += a.w + b.w;
        if (zr) {
            float4 u = zr[g * hv + q];
            v.x += u.x; v.y += u.y; v.z += u.z; v.w += u.w;
        }
        z[g] = v;
    }
    float4 cold = first ? make_float4(0.f, 0.f, 0.f, 0.f) : ((float4*)c_st)[idx];
    float4 cn;
    float hv4[4];
#pragma unroll
    for (int e = 0; e < 4; ++e) {
        float zi = (&z[0].x)[e], zf = (&z[1].x)[e], zg = (&z[2].x)[e], zo = (&z[3].x)[e];
        float ig = sigmoidf_(zi), fg = sigmoidf_(zf);
        float gg = tanhf(zg), og = sigmoidf_(zo);
        float cc = fg * (&cold.x)[e] + ig * gg;
        (&cn.x)[e] = cc;
        hv4[e] = og * tanhf(cc);
    }
    ((float4*)c_st)[idx] = cn;
    ((__half2*)h_out)[idx * 2]     = __floats2half2_rn(hv4[0], hv4[1]);
    ((__half2*)h_out)[idx * 2 + 1] = __floats2half2_rn(hv4[2], hv4[3]);
}

// ---------------- JK attention scores + softmax ------------------------------
__global__ void jk_score_kernel(const float* __restrict__ attw,
                                const float* __restrict__ attb,
                                float* __restrict__ wout)
{
    int gtid = blockIdx.x * blockDim.x + threadIdx.x;
    int node = gtid >> 5;
    int lane = gtid & 31;
    if (node >= NN) return;
    float sc[3];
#pragma unroll
    for (int t = 0; t < 3; ++t) {
        const __half* f = d_fwdh  + (size_t)t * NN * JKH + (size_t)node * JKH;
        const __half* b = d_bwdph + (size_t)t * NN * JKH + (size_t)node * JKH;
        float s = 0.f;
        for (int k = lane; k < JKH; k += 32)
            s += __half2float(f[k]) * attw[k] + __half2float(b[k]) * attw[JKH + k];
#pragma unroll
        for (int off = 16; off > 0; off >>= 1)
            s += __shfl_xor_sync(0xffffffffu, s, off);
        sc[t] = s + attb[0];
    }
    if (lane == 0) {
        float m = fmaxf(sc[0], fmaxf(sc[1], sc[2]));
        float e0 = expf(sc[0] - m), e1 = expf(sc[1] - m), e2 = expf(sc[2] - m);
        float inv = 1.f / (e0 + e1 + e2);
        wout[node * 3 + 0] = e0 * inv;
        wout[node * 3 + 1] = e1 * inv;
        wout[node * 3 + 2] = e2 * inv;
    }
}

__global__ void jk_combine_kernel(float* __restrict__ out) {
    int idx = blockIdx.x * blockDim.x + threadIdx.x;
    if (idx >= NN * 64) return;
    int n = idx >> 6;
    float w0 = d_w[n * 3 + 0], w1 = d_w[n * 3 + 1], w2 = d_w[n * 3 + 2];
    float2 a = __half22float2(((const __half2*)d_xcath)[idx]);
    float2 b = __half22float2(((const __half2*)(d_xcath + NN * CC))[idx]);
    float2 c = __half22float2(((const __half2*)(d_xcath + 2 * NN * CC))[idx]);
    ((float2*)out)[idx] = make_float2(w0 * a.x + w1 * b.x + w2 * c.x,
                                      w0 * a.y + w1 * b.y + w2 * c.y);
}

// ---------------------------------------------------------------------------
static inline int cdiv(int a, int b) { return (a + b - 1) / b; }

extern "C" void kernel_launch(void* const* d_in, const int* in_sizes, int n_in,
                              void* d_out, int out_size)
{
    const void* ei = nullptr;
    const float* x = nullptr;
    const float* wp[23];
    int wcount = 0;
    for (int i = 0; i < n_in; ++i) {
        if (in_sizes[i] == 2 * EE)       ei = d_in[i];
        else if (in_sizes[i] == NN * CC) x  = (const float*)d_in[i];
        else if (wcount < 23)            wp[wcount++] = (const float*)d_in[i];
    }
    const float *Wl1 = wp[0],  *bl1 = wp[1],  *Wr1 = wp[2];
    const float *Wl2 = wp[3],  *bl2 = wp[4],  *Wr2 = wp[5];
    const float *Wl3 = wp[6],  *bl3 = wp[7],  *Wr3 = wp[8];
    const float *Wih_a = wp[9],  *Whh_a = wp[10], *bih_a = wp[11], *bhh_a = wp[12];
    const float *Wih_f = wp[13], *Whh_f = wp[14], *bih_f = wp[15], *bhh_f = wp[16];
    const float *Wih_b = wp[17], *Whh_b = wp[18], *bih_b = wp[19], *bhh_b = wp[20];
    const float *att_w = wp[21], *att_b = wp[22];

    __half *xh, *aggh, *xcath, *hAh, *fwdh, *bwdph, *wh;
    float *cA, *Pa, *Pf, *Pb, *Z, *cF, *cB, *wbuf;
    int* srcp;
    cudaGetSymbolAddress((void**)&srcp,  d_src);
    cudaGetSymbolAddress((void**)&xh,    d_xh);
    cudaGetSymbolAddress((void**)&aggh,  d_aggh);
    cudaGetSymbolAddress((void**)&xcath, d_xcath);
    cudaGetSymbolAddress((void**)&hAh,   d_hAh);
    cudaGetSymbolAddress((void**)&cA,    d_cA);
    cudaGetSymbolAddress((void**)&Pa,    d_Pa);
    cudaGetSymbolAddress((void**)&Pf,    d_Pf);
    cudaGetSymbolAddress((void**)&Pb,    d_Pb);
    cudaGetSymbolAddress((void**)&Z,     d_Z);
    cudaGetSymbolAddress((void**)&fwdh,  d_fwdh);
    cudaGetSymbolAddress((void**)&bwdph, d_bwdph);
    cudaGetSymbolAddress((void**)&cF,    d_cF);
    cudaGetSymbolAddress((void**)&cB,    d_cB);
    cudaGetSymbolAddress((void**)&wbuf,  d_w);
    cudaGetSymbolAddress((void**)&wh,    d_wh);

    __half* hWl1 = wh;                 __half* hWr1 = hWl1 + 16384;
    __half* hWl2 = hWr1 + 16384;       __half* hWr2 = hWl2 + 16384;
    __half* hWl3 = hWr2 + 16384;       __half* hWr3 = hWl3 + 16384;
    __half* hWih_a = hWr3 + 16384;     __half* hWhh_a = hWih_a + 65536;
    __half* hWih_f = hWhh_a + 65536;   __half* hWhh_f = hWih_f + 98304;
    __half* hWih_b = hWhh_f + 147456;  __half* hWhh_b = hWih_b + 98304;

    __half* h1h = xcath;
    __half* h2h = xcath + NN * CC;
    __half* h3h = xcath + 2 * NN * CC;
    float* out = (float*)d_out;

    cudaFuncSetAttribute(h16_gemm_kernel,
                         cudaFuncAttributeMaxDynamicSharedMemorySize, SMEM_BYTES);

    const int NH2_BLK = cdiv(NN * 64, 256);
    const int NC_BLK4 = cdiv(NN * CC / 4, 256);
    const int NJ_BLK4 = cdiv(NN * JKH / 4, 256);
    dim3 g128(cdiv(NN, BM), 1);
    dim3 g512(cdiv(NN, BM), 4);
    dim3 g768(cdiv(NN, BM), 6);
    dim3 g768x3(cdiv(3 * NN, BM), 6);

    // ---- prep: edge index + fp16 conversion (batched weights, 1 launch)
    detect_idx_kernel<<<1, 32>>>(ei);
    convert_src_kernel<<<cdiv(EE, 256), 256>>>(ei);
    cvt_half_kernel<<<cdiv(NN * CC / 4, 256), 256>>>(x, xh, NN * CC / 4);

    {
        CvtJobs jobs;
        const float* srcs[NSEG] = {Wl1, Wr1, Wl2, Wr2, Wl3, Wr3,
                                   Wih_a, Whh_a, Wih_f, Whh_f, Wih_b, Whh_b, nullptr};
        __half* dsts[NSEG] = {hWl1, hWr1, hWl2, hWr2, hWl3, hWr3,
                              hWih_a, hWhh_a, hWih_f, hWhh_f, hWih_b, hWhh_b, nullptr};
        int n4s[NSEG] = {4096, 4096, 4096, 4096, 4096, 4096,
                         16384, 16384, 24576, 36864, 24576, 36864, 0};
        int acc = 0;
        for (int s = 0; s < NSEG; ++s) {
            jobs.src[s] = srcs[s] ? srcs[s] : Wl1;   // harmless pad
            jobs.dst[s] = dsts[s] ? dsts[s] : hWl1;
            acc += n4s[s];
            jobs.end4[s] = acc;
        }
        cvt_half_multi_kernel<<<cdiv(acc, 256), 256>>>(jobs, acc);
    }

    // ---- layer 1: mean SAGE + relu -> h1 (fp16)
    agg_mean_kernel<<<NH2_BLK, 256>>>(xh, aggh);
    h16_gemm_kernel<<<g128, 256, SMEM_BYTES>>>(aggh, xh, hWl1, hWr1, bl1,
                                               nullptr, h1h, NN, 128, 128, 128, 1);

    // ---- layer 2: max SAGE + relu -> h2 (fp16)
    agg_max_kernel<<<NH2_BLK, 256>>>(h1h, aggh);
    h16_gemm_kernel<<<g128, 256, SMEM_BYTES>>>(aggh, h1h, hWl2, hWr2, bl2,
                                               nullptr, h2h, NN, 128, 128, 128, 1);

    // ---- layer 3: LSTM aggregation (hoisted input projection, fp32 P/Z)
    h16_gemm_kernel<<<g512, 256, SMEM_BYTES>>>(h2h, nullptr, hWih_a, nullptr, nullptr,
                                               Pa, nullptr, NN, 512, 128, 0, 0);
    for (int t = 0; t < KK; ++t) {
        const float* zr = nullptr;
        if (t > 0) {
            h16_gemm_kernel<<<g512, 256, SMEM_BYTES>>>(hAh, nullptr, hWhh_a, nullptr, nullptr,
                                                       Z, nullptr, NN, 512, 128, 0, 0);
            zr = Z;
        }
        lstm_gates_kernel<<<NC_BLK4, 256>>>(zr, Pa, srcp, t, bih_a, bhh_a,
                                            hAh, cA, 128, t == 0);
    }
    h16_gemm_kernel<<<g128, 256, SMEM_BYTES>>>(hAh, h2h, hWl3, hWr3, bl3,
                                               nullptr, h3h, NN, 128, 128, 128, 0);

    // ---- JK bi-LSTM: batched input projections (fp32 P)
    h16_gemm_kernel<<<g768x3, 256, SMEM_BYTES>>>(xcath, nullptr, hWih_f, nullptr, nullptr,
                                                 Pf, nullptr, 3 * NN, 768, 128, 0, 0);
    h16_gemm_kernel<<<g768x3, 256, SMEM_BYTES>>>(xcath, nullptr, hWih_b, nullptr, nullptr,
                                                 Pb, nullptr, 3 * NN, 768, 128, 0, 0);

    for (int t = 0; t < 3; ++t) {
        const float* zrF = nullptr;
        if (t > 0) {
            h16_gemm_kernel<<<g768, 256, SMEM_BYTES>>>(
                fwdh + (size_t)(t - 1) * NN * JKH, nullptr, hWhh_f, nullptr, nullptr,
                Z, nullptr, NN, 768, JKH, 0, 0);
            zrF = Z;
        }
        lstm_gates_kernel<<<NJ_BLK4, 256>>>(zrF, Pf + (size_t)t * NN * 768, nullptr, 0,
                                            bih_f, bhh_f,
                                            fwdh + (size_t)t * NN * JKH, cF, JKH, t == 0);
        const float* zrB = nullptr;
        if (t > 0) {
            h16_gemm_kernel<<<g768, 256, SMEM_BYTES>>>(
                bwdph + (size_t)(3 - t) * NN * JKH, nullptr, hWhh_b, nullptr, nullptr,
                Z, nullptr, NN, 768, JKH, 0, 0);
            zrB = Z;
        }
        lstm_gates_kernel<<<NJ_BLK4, 256>>>(zrB, Pb + (size_t)(2 - t) * NN * 768, nullptr, 0,
                                            bih_b, bhh_b,
                                            bwdph + (size_t)(2 - t) * NN * JKH, cB, JKH, t == 0);
    }

    // ---- attention + combine
    jk_score_kernel<<<cdiv(NN * 32, 256), 256>>>(att_w, att_b, wbuf);
    jk_combine_kernel<<<NH2_BLK, 256>>>(out);

    (void)out_size;
}

// round 11
// speedup vs baseline: 2.0262x; 1.1195x over previous
#include <cuda_runtime.h>
#include <cuda_fp16.h>
#include <math.h>
#include <stdint.h>

// ---------------------------------------------------------------------------
// GraphSAGE (mean -> max -> lstm aggr -> JK bi-LSTM), N=50000, K=16, C=128.
// Round 11 (= round 10 resubmit after infra failure): fp16 mma GEMM + fp16
// storage for P/Z pre-activation buffers. Gates math stays fp32.
// ---------------------------------------------------------------------------

#define NN 50000
#define KK 16
#define EE (NN * KK)
#define CC 128
#define JKH 192

#define BM 128
#define BN 128
#define BKT 32                      // halves per K-tile
#define RSTRH 40                    // halves per smem row (32 + 8 pad) = 80 B
#define RSTRW 20                    // words per smem row
#define TILE_B (BM * RSTRH * 2)     // 10240 bytes per tile side
#define STAGE_B (2 * TILE_B)        // 20480
#define SMEM_BYTES (3 * STAGE_B)    // 61440

// ---------------- static device scratch -------------------------------------
__device__ int    d_src[EE];
__device__ int    d_is64;
__device__ __half d_xh[NN * CC];
__device__ __half d_aggh[NN * CC];
__device__ __half d_xcath[3 * NN * CC];         // h1 | h2 | h3 (fp16)
__device__ __half d_hAh[NN * CC];
__device__ float  d_cA[NN * CC];
__device__ __half d_Pa[NN * 512];               // fp16 pre-activations
__device__ __half d_Pf[3 * NN * 768];
__device__ __half d_Pb[3 * NN * 768];
__device__ __half d_Z[NN * 768];
__device__ __half d_fwdh[3 * NN * JKH];
__device__ __half d_bwdph[3 * NN * JKH];
__device__ float  d_cF[NN * JKH];
__device__ float  d_cB[NN * JKH];
__device__ float  d_w[NN * 3];
__device__ __half d_wh[720896];                 // fp16 weights arena

__device__ __forceinline__ float sigmoidf_(float x) { return 1.f / (1.f + expf(-x)); }

// ---------------- edge-index probe + convert ---------------------------------
__global__ void detect_idx_kernel(const void* ei) {
    const long long* p = (const long long*)ei;
    int lane = threadIdx.x;
    int ok = 1;
#pragma unroll
    for (int i = 0; i < 4; ++i) {
        long long v = p[lane * 4 + i];
        if (v < 0 || v >= NN) ok = 0;
    }
    unsigned m = __ballot_sync(0xffffffffu, ok);
    if (lane == 0) d_is64 = (m == 0xffffffffu) ? 1 : 0;
}

__global__ void convert_src_kernel(const void* ei) {
    int idx = blockIdx.x * blockDim.x + threadIdx.x;
    if (idx >= EE) return;
    if (d_is64) d_src[idx] = (int)((const long long*)ei)[idx];
    else        d_src[idx] = ((const int*)ei)[idx];
}

// ---------------- fp32 -> fp16 conversion ------------------------------------
__global__ void cvt_half_kernel(const float* __restrict__ in, __half* __restrict__ out, int n4) {
    int i = blockIdx.x * blockDim.x + threadIdx.x;
    if (i >= n4) return;
    float4 v = ((const float4*)in)[i];
    ((__half2*)out)[i * 2]     = __floats2half2_rn(v.x, v.y);
    ((__half2*)out)[i * 2 + 1] = __floats2half2_rn(v.z, v.w);
}

// Batched multi-segment conversion: one launch for all weight tensors.
#define NSEG 13
struct CvtJobs {
    const float* src[NSEG];
    __half*      dst[NSEG];
    int          end4[NSEG];   // cumulative float4 counts
};

__global__ void cvt_half_multi_kernel(CvtJobs jobs, int total4) {
    int i = blockIdx.x * blockDim.x + threadIdx.x;
    if (i >= total4) return;
    int seg = 0;
#pragma unroll
    for (int s = 0; s < NSEG; ++s)
        if (i >= jobs.end4[s]) seg = s + 1;
    int base = (seg == 0) ? 0 : jobs.end4[seg - 1];
    int j = i - base;
    float4 v = ((const float4*)jobs.src[seg])[j];
    ((__half2*)jobs.dst[seg])[j * 2]     = __floats2half2_rn(v.x, v.y);
    ((__half2*)jobs.dst[seg])[j * 2 + 1] = __floats2half2_rn(v.z, v.w);
}

// ---------------- neighbor aggregations (half2) ------------------------------
__global__ void agg_mean_kernel(const __half* __restrict__ X, __half* __restrict__ out) {
    int idx = blockIdx.x * blockDim.x + threadIdx.x;
    if (idx >= NN * 64) return;
    int n = idx >> 6, c2 = idx & 63;
    const int* s = d_src + n * KK;
    float ax = 0.f, ay = 0.f;
#pragma unroll
    for (int j = 0; j < KK; ++j) {
        float2 v = __half22float2(*(const __half2*)(X + (size_t)s[j] * CC + 2 * c2));
        ax += v.x; ay += v.y;
    }
    ((__half2*)out)[idx] = __floats2half2_rn(ax * (1.f / 16.f), ay * (1.f / 16.f));
}

__global__ void agg_max_kernel(const __half* __restrict__ X, __half* __restrict__ out) {
    int idx = blockIdx.x * blockDim.x + threadIdx.x;
    if (idx >= NN * 64) return;
    int n = idx >> 6, c2 = idx & 63;
    const int* s = d_src + n * KK;
    float ax = -INFINITY, ay = -INFINITY;
#pragma unroll
    for (int j = 0; j < KK; ++j) {
        float2 v = __half22float2(*(const __half2*)(X + (size_t)s[j] * CC + 2 * c2));
        ax = fmaxf(ax, v.x); ay = fmaxf(ay, v.y);
    }
    ((__half2*)out)[idx] = __floats2half2_rn(ax, ay);
}

// ---------------- fp16 GEMM (cp.async 3-stage, m16n8k16) ---------------------
// Cout = act( A[MxK1]@W1^T + B2[MxK2]@W2^T + bias ); K-concat over halves.
// Writes CoutF (fp32) if non-null else CoutH (fp16). relu: apply max(0,.)
__global__ __launch_bounds__(256, 2) void h16_gemm_kernel(
    const __half* __restrict__ A, const __half* __restrict__ B2,
    const __half* __restrict__ W1, const __half* __restrict__ W2,
    const float* __restrict__ bias,
    float* __restrict__ CoutF, __half* __restrict__ CoutH,
    int M, int Nc, int K1, int K2, int relu)
{
    extern __shared__ __align__(16) char smraw[];
    const int tid = threadIdx.x, wid = tid >> 5, lane = tid & 31;
    const int grp = lane >> 2, tig = lane & 3;
    const int warpM = wid >> 1, warpN = wid & 1;
    const int rowBase = blockIdx.x * BM, colBase = blockIdx.y * BN;
    const int Ktot = K1 + K2, nk = Ktot / BKT;
    const int cr = tid >> 2;               // row 0..63, +64 on second pass
    const int chh = (tid & 3) * 8;         // half offset within row

    float c[2][8][4];
#pragma unroll
    for (int mt = 0; mt < 2; ++mt)
#pragma unroll
        for (int nt = 0; nt < 8; ++nt)
#pragma unroll
            for (int i = 0; i < 4; ++i) c[mt][nt][i] = 0.f;

    auto issue = [&](int it, int s) {
        if (it < nk) {
            int kk = it * BKT;
            const __half* asrc; const __half* wsrc; int ld, kb;
            if (kk < K1) { asrc = A;  wsrc = W1; ld = K1; kb = kk; }
            else         { asrc = B2; wsrc = W2; ld = K2; kb = kk - K1; }
            char* smA = smraw + s * STAGE_B;
            char* smB = smA + TILE_B;
#pragma unroll
            for (int p = 0; p < 2; ++p) {
                int r = cr + p * 64;
                int row = rowBase + r;
                int rc = (row < M) ? row : 0;
                uint32_t dst = (uint32_t)__cvta_generic_to_shared(smA + r * (RSTRH * 2) + chh * 2);
                const __half* g = asrc + (size_t)rc * ld + kb + chh;
                int sz = (row < M) ? 16 : 0;
                asm volatile("cp.async.cg.shared.global [%0], [%1], 16, %2;\n"
                             :: "r"(dst), "l"(g), "r"(sz));
            }
#pragma unroll
            for (int p = 0; p < 2; ++p) {
                int r = cr + p * 64;
                uint32_t dst = (uint32_t)__cvta_generic_to_shared(smB + r * (RSTRH * 2) + chh * 2);
                const __half* g = wsrc + (size_t)(colBase + r) * ld + kb + chh;
                asm volatile("cp.async.cg.shared.global [%0], [%1], 16;\n"
                             :: "r"(dst), "l"(g));
            }
        }
        asm volatile("cp.async.commit_group;\n");
    };

    issue(0, 0);
    issue(1, 1);

    for (int it = 0; it < nk; ++it) {
        asm volatile("cp.async.wait_group 1;\n");
        __syncthreads();
        const int s = it % 3;
        const uint32_t* smA = (const uint32_t*)(smraw + s * STAGE_B);
        const uint32_t* smB = (const uint32_t*)(smraw + s * STAGE_B + TILE_B);
        const int m0 = warpM * 32, n0 = warpN * 64;
#pragma unroll
        for (int kt = 0; kt < 2; ++kt) {
            const int wk = kt * 8;
            uint32_t af[2][4], bf[8][2];
#pragma unroll
            for (int mt = 0; mt < 2; ++mt) {
                int m = m0 + mt * 16;
                af[mt][0] = smA[(m + grp) * RSTRW + wk + tig];
                af[mt][1] = smA[(m + 8 + grp) * RSTRW + wk + tig];
                af[mt][2] = smA[(m + grp) * RSTRW + wk + tig + 4];
                af[mt][3] = smA[(m + 8 + grp) * RSTRW + wk + tig + 4];
            }
#pragma unroll
            for (int nt = 0; nt < 8; ++nt) {
                int n = n0 + nt * 8;
                bf[nt][0] = smB[(n + grp) * RSTRW + wk + tig];
                bf[nt][1] = smB[(n + grp) * RSTRW + wk + tig + 4];
            }
#pragma unroll
            for (int mt = 0; mt < 2; ++mt)
#pragma unroll
                for (int nt = 0; nt < 8; ++nt) {
                    asm volatile(
                        "mma.sync.aligned.m16n8k16.row.col.f32.f16.f16.f32 "
                        "{%0,%1,%2,%3}, {%4,%5,%6,%7}, {%8,%9}, {%0,%1,%2,%3};\n"
                        : "+f"(c[mt][nt][0]), "+f"(c[mt][nt][1]),
                          "+f"(c[mt][nt][2]), "+f"(c[mt][nt][3])
                        : "r"(af[mt][0]), "r"(af[mt][1]), "r"(af[mt][2]), "r"(af[mt][3]),
                          "r"(bf[nt][0]), "r"(bf[nt][1]));
                }
        }
        issue(it + 2, (it + 2) % 3);
    }

#pragma unroll
    for (int mt = 0; mt < 2; ++mt) {
#pragma unroll
        for (int nt = 0; nt < 8; ++nt) {
            int col = colBase + warpN * 64 + nt * 8 + tig * 2;
            float b0 = bias ? bias[col] : 0.f;
            float b1 = bias ? bias[col + 1] : 0.f;
            int r0 = rowBase + warpM * 32 + mt * 16 + grp;
            int r1 = r0 + 8;
            float v0 = c[mt][nt][0] + b0, v1 = c[mt][nt][1] + b1;
            float v2 = c[mt][nt][2] + b0, v3 = c[mt][nt][3] + b1;
            if (relu) { v0 = fmaxf(v0, 0.f); v1 = fmaxf(v1, 0.f);
                        v2 = fmaxf(v2, 0.f); v3 = fmaxf(v3, 0.f); }
            if (CoutF) {
                if (r0 < M) *(float2*)(CoutF + (size_t)r0 * Nc + col) = make_float2(v0, v1);
                if (r1 < M) *(float2*)(CoutF + (size_t)r1 * Nc + col) = make_float2(v2, v3);
            } else {
                if (r0 < M) *(__half2*)(CoutH + (size_t)r0 * Nc + col) = __floats2half2_rn(v0, v1);
                if (r1 < M) *(__half2*)(CoutH + (size_t)r1 * Nc + col) = __floats2half2_rn(v2, v3);
            }
        }
    }
}

// ---------------- LSTM gates: z = Zrec + P[gathered] + biases ----------------
// P/Zrec fp16; biases fp32; h_out fp16; c_st fp32.
__global__ void lstm_gates_kernel(
    const __half* __restrict__ Zrec,
    const __half* __restrict__ P,
    const int* __restrict__ src, int t,
    const float* __restrict__ bih, const float* __restrict__ bhh,
    __half* __restrict__ h_out, float* __restrict__ c_st,
    int H, int first)
{
    int hv = H >> 2;
    int idx = blockIdx.x * blockDim.x + threadIdx.x;
    if (idx >= NN * hv) return;
    int n = idx / hv, q = idx - n * hv;
    int pn = src ? src[n * KK + t] : n;
    const uint2* pr = (const uint2*)(P + (size_t)pn * 4 * H);     // 4 halves per uint2
    const uint2* zr = Zrec ? (const uint2*)(Zrec + (size_t)n * 4 * H) : nullptr;
    const float4* b1 = (const float4*)bih;
    const float4* b2 = (const float4*)bhh;

    float4 z[4];
#pragma unroll
    for (int g = 0; g < 4; ++g) {
        uint2 pu = pr[g * hv + q];
        float2 pa = __half22float2(*(const __half2*)&pu.x);
        float2 pb = __half22float2(*(const __half2*)&pu.y);
        float4 a = b1[g * hv + q], b = b2[g * hv + q];
        float4 v = make_float4(pa.x + a.x + b.x, pa.y + a.y + b.y,
                               pb.x + a.z + b.z, pb.y + a.w + b.w);
        if (zr) {
            uint2 zu = zr[g * hv + q];
            float2 za = __half22float2(*(const __half2*)&zu.x);
            float2 zb = __half22float2(*(const __half2*)&zu.y);
            v.x += za.x; v.y += za.y; v.z += zb.x; v.w += zb.y;
        }
        z[g] = v;
    }
    float4 cold = first ? make_float4(0.f, 0.f, 0.f, 0.f) : ((float4*)c_st)[idx];
    float4 cn;
    float hv4[4];
#pragma unroll
    for (int e = 0; e < 4; ++e) {
        float zi = (&z[0].x)[e], zf = (&z[1].x)[e], zg = (&z[2].x)[e], zo = (&z[3].x)[e];
        float ig = sigmoidf_(zi), fg = sigmoidf_(zf);
        float gg = tanhf(zg), og = sigmoidf_(zo);
        float cc = fg * (&cold.x)[e] + ig * gg;
        (&cn.x)[e] = cc;
        hv4[e] = og * tanhf(cc);
    }
    ((float4*)c_st)[idx] = cn;
    ((__half2*)h_out)[idx * 2]     = __floats2half2_rn(hv4[0], hv4[1]);
    ((__half2*)h_out)[idx * 2 + 1] = __floats2half2_rn(hv4[2], hv4[3]);
}

// ---------------- JK attention scores + softmax ------------------------------
__global__ void jk_score_kernel(const float* __restrict__ attw,
                                const float* __restrict__ attb,
                                float* __restrict__ wout)
{
    int gtid = blockIdx.x * blockDim.x + threadIdx.x;
    int node = gtid >> 5;
    int lane = gtid & 31;
    if (node >= NN) return;
    float sc[3];
#pragma unroll
    for (int t = 0; t < 3; ++t) {
        const __half* f = d_fwdh  + (size_t)t * NN * JKH + (size_t)node * JKH;
        const __half* b = d_bwdph + (size_t)t * NN * JKH + (size_t)node * JKH;
        float s = 0.f;
        for (int k = lane; k < JKH; k += 32)
            s += __half2float(f[k]) * attw[k] + __half2float(b[k]) * attw[JKH + k];
#pragma unroll
        for (int off = 16; off > 0; off >>= 1)
            s += __shfl_xor_sync(0xffffffffu, s, off);
        sc[t] = s + attb[0];
    }
    if (lane == 0) {
        float m = fmaxf(sc[0], fmaxf(sc[1], sc[2]));
        float e0 = expf(sc[0] - m), e1 = expf(sc[1] - m), e2 = expf(sc[2] - m);
        float inv = 1.f / (e0 + e1 + e2);
        wout[node * 3 + 0] = e0 * inv;
        wout[node * 3 + 1] = e1 * inv;
        wout[node * 3 + 2] = e2 * inv;
    }
}

__global__ void jk_combine_kernel(float* __restrict__ out) {
    int idx = blockIdx.x * blockDim.x + threadIdx.x;
    if (idx >= NN * 64) return;
    int n = idx >> 6;
    float w0 = d_w[n * 3 + 0], w1 = d_w[n * 3 + 1], w2 = d_w[n * 3 + 2];
    float2 a = __half22float2(((const __half2*)d_xcath)[idx]);
    float2 b = __half22float2(((const __half2*)(d_xcath + NN * CC))[idx]);
    float2 c = __half22float2(((const __half2*)(d_xcath + 2 * NN * CC))[idx]);
    ((float2*)out)[idx] = make_float2(w0 * a.x + w1 * b.x + w2 * c.x,
                                      w0 * a.y + w1 * b.y + w2 * c.y);
}

// ---------------------------------------------------------------------------
static inline int cdiv(int a, int b) { return (a + b - 1) / b; }

extern "C" void kernel_launch(void* const* d_in, const int* in_sizes, int n_in,
                              void* d_out, int out_size)
{
    const void* ei = nullptr;
    const float* x = nullptr;
    const float* wp[23];
    int wcount = 0;
    for (int i = 0; i < n_in; ++i) {
        if (in_sizes[i] == 2 * EE)       ei = d_in[i];
        else if (in_sizes[i] == NN * CC) x  = (const float*)d_in[i];
        else if (wcount < 23)            wp[wcount++] = (const float*)d_in[i];
    }
    const float *Wl1 = wp[0],  *bl1 = wp[1],  *Wr1 = wp[2];
    const float *Wl2 = wp[3],  *bl2 = wp[4],  *Wr2 = wp[5];
    const float *Wl3 = wp[6],  *bl3 = wp[7],  *Wr3 = wp[8];
    const float *Wih_a = wp[9],  *Whh_a = wp[10], *bih_a = wp[11], *bhh_a = wp[12];
    const float *Wih_f = wp[13], *Whh_f = wp[14], *bih_f = wp[15], *bhh_f = wp[16];
    const float *Wih_b = wp[17], *Whh_b = wp[18], *bih_b = wp[19], *bhh_b = wp[20];
    const float *att_w = wp[21], *att_b = wp[22];

    __half *xh, *aggh, *xcath, *hAh, *fwdh, *bwdph, *wh, *Pa, *Pf, *Pb, *Z;
    float *cA, *cF, *cB, *wbuf;
    int* srcp;
    cudaGetSymbolAddress((void**)&srcp,  d_src);
    cudaGetSymbolAddress((void**)&xh,    d_xh);
    cudaGetSymbolAddress((void**)&aggh,  d_aggh);
    cudaGetSymbolAddress((void**)&xcath, d_xcath);
    cudaGetSymbolAddress((void**)&hAh,   d_hAh);
    cudaGetSymbolAddress((void**)&cA,    d_cA);
    cudaGetSymbolAddress((void**)&Pa,    d_Pa);
    cudaGetSymbolAddress((void**)&Pf,    d_Pf);
    cudaGetSymbolAddress((void**)&Pb,    d_Pb);
    cudaGetSymbolAddress((void**)&Z,     d_Z);
    cudaGetSymbolAddress((void**)&fwdh,  d_fwdh);
    cudaGetSymbolAddress((void**)&bwdph, d_bwdph);
    cudaGetSymbolAddress((void**)&cF,    d_cF);
    cudaGetSymbolAddress((void**)&cB,    d_cB);
    cudaGetSymbolAddress((void**)&wbuf,  d_w);
    cudaGetSymbolAddress((void**)&wh,    d_wh);

    __half* hWl1 = wh;                 __half* hWr1 = hWl1 + 16384;
    __half* hWl2 = hWr1 + 16384;       __half* hWr2 = hWl2 + 16384;
    __half* hWl3 = hWr2 + 16384;       __half* hWr3 = hWl3 + 16384;
    __half* hWih_a = hWr3 + 16384;     __half* hWhh_a = hWih_a + 65536;
    __half* hWih_f = hWhh_a + 65536;   __half* hWhh_f = hWih_f + 98304;
    __half* hWih_b = hWhh_f + 147456;  __half* hWhh_b = hWih_b + 98304;

    __half* h1h = xcath;
    __half* h2h = xcath + NN * CC;
    __half* h3h = xcath + 2 * NN * CC;
    float* out = (float*)d_out;

    cudaFuncSetAttribute(h16_gemm_kernel,
                         cudaFuncAttributeMaxDynamicSharedMemorySize, SMEM_BYTES);

    const int NH2_BLK = cdiv(NN * 64, 256);
    const int NC_BLK4 = cdiv(NN * CC / 4, 256);
    const int NJ_BLK4 = cdiv(NN * JKH / 4, 256);
    dim3 g128(cdiv(NN, BM), 1);
    dim3 g512(cdiv(NN, BM), 4);
    dim3 g768(cdiv(NN, BM), 6);
    dim3 g768x3(cdiv(3 * NN, BM), 6);

    // ---- prep: edge index + fp16 conversion (batched weights, 1 launch)
    detect_idx_kernel<<<1, 32>>>(ei);
    convert_src_kernel<<<cdiv(EE, 256), 256>>>(ei);
    cvt_half_kernel<<<cdiv(NN * CC / 4, 256), 256>>>(x, xh, NN * CC / 4);

    {
        CvtJobs jobs;
        const float* srcs[NSEG] = {Wl1, Wr1, Wl2, Wr2, Wl3, Wr3,
                                   Wih_a, Whh_a, Wih_f, Whh_f, Wih_b, Whh_b, nullptr};
        __half* dsts[NSEG] = {hWl1, hWr1, hWl2, hWr2, hWl3, hWr3,
                              hWih_a, hWhh_a, hWih_f, hWhh_f, hWih_b, hWhh_b, nullptr};
        int n4s[NSEG] = {4096, 4096, 4096, 4096, 4096, 4096,
                         16384, 16384, 24576, 36864, 24576, 36864, 0};
        int acc = 0;
        for (int s = 0; s < NSEG; ++s) {
            jobs.src[s] = srcs[s] ? srcs[s] : Wl1;
            jobs.dst[s] = dsts[s] ? dsts[s] : hWl1;
            acc += n4s[s];
            jobs.end4[s] = acc;
        }
        cvt_half_multi_kernel<<<cdiv(acc, 256), 256>>>(jobs, acc);
    }

    // ---- layer 1: mean SAGE + relu -> h1 (fp16)
    agg_mean_kernel<<<NH2_BLK, 256>>>(xh, aggh);
    h16_gemm_kernel<<<g128, 256, SMEM_BYTES>>>(aggh, xh, hWl1, hWr1, bl1,
                                               nullptr, h1h, NN, 128, 128, 128, 1);

    // ---- layer 2: max SAGE + relu -> h2 (fp16)
    agg_max_kernel<<<NH2_BLK, 256>>>(h1h, aggh);
    h16_gemm_kernel<<<g128, 256, SMEM_BYTES>>>(aggh, h1h, hWl2, hWr2, bl2,
                                               nullptr, h2h, NN, 128, 128, 128, 1);

    // ---- layer 3: LSTM aggregation (hoisted input projection, fp16 P/Z)
    h16_gemm_kernel<<<g512, 256, SMEM_BYTES>>>(h2h, nullptr, hWih_a, nullptr, nullptr,
                                               nullptr, Pa, NN, 512, 128, 0, 0);
    for (int t = 0; t < KK; ++t) {
        const __half* zr = nullptr;
        if (t > 0) {
            h16_gemm_kernel<<<g512, 256, SMEM_BYTES>>>(hAh, nullptr, hWhh_a, nullptr, nullptr,
                                                       nullptr, Z, NN, 512, 128, 0, 0);
            zr = Z;
        }
        lstm_gates_kernel<<<NC_BLK4, 256>>>(zr, Pa, srcp, t, bih_a, bhh_a,
                                            hAh, cA, 128, t == 0);
    }
    h16_gemm_kernel<<<g128, 256, SMEM_BYTES>>>(hAh, h2h, hWl3, hWr3, bl3,
                                               nullptr, h3h, NN, 128, 128, 128, 0);

    // ---- JK bi-LSTM: batched input projections (fp16 P)
    h16_gemm_kernel<<<g768x3, 256, SMEM_BYTES>>>(xcath, nullptr, hWih_f, nullptr, nullptr,
                                                 nullptr, Pf, 3 * NN, 768, 128, 0, 0);
    h16_gemm_kernel<<<g768x3, 256, SMEM_BYTES>>>(xcath, nullptr, hWih_b, nullptr, nullptr,
                                                 nullptr, Pb, 3 * NN, 768, 128, 0, 0);

    for (int t = 0; t < 3; ++t) {
        const __half* zrF = nullptr;
        if (t > 0) {
            h16_gemm_kernel<<<g768, 256, SMEM_BYTES>>>(
                fwdh + (size_t)(t - 1) * NN * JKH, nullptr, hWhh_f, nullptr, nullptr,
                nullptr, Z, NN, 768, JKH, 0, 0);
            zrF = Z;
        }
        lstm_gates_kernel<<<NJ_BLK4, 256>>>(zrF, Pf + (size_t)t * NN * 768, nullptr, 0,
                                            bih_f, bhh_f,
                                            fwdh + (size_t)t * NN * JKH, cF, JKH, t == 0);
        const __half* zrB = nullptr;
        if (t > 0) {
            h16_gemm_kernel<<<g768, 256, SMEM_BYTES>>>(
                bwdph + (size_t)(3 - t) * NN * JKH, nullptr, hWhh_b, nullptr, nullptr,
                nullptr, Z, NN, 768, JKH, 0, 0);
            zrB = Z;
        }
        lstm_gates_kernel<<<NJ_BLK4, 256>>>(zrB, Pb + (size_t)(2 - t) * NN * 768, nullptr, 0,
                                            bih_b, bhh_b,
                                            bwdph + (size_t)(2 - t) * NN * JKH, cB, JKH, t == 0);
    }

    // ---- attention + combine
    jk_score_kernel<<<cdiv(NN * 32, 256), 256>>>(att_w, att_b, wbuf);
    jk_combine_kernel<<<NH2_BLK, 256>>>(out);

    (void)out_size;
}

// round 12
// speedup vs baseline: 2.0791x; 1.0261x over previous
#include <cuda_runtime.h>
#include <cuda_fp16.h>
#include <math.h>
#include <stdint.h>

// ---------------------------------------------------------------------------
// GraphSAGE (mean -> max -> lstm aggr -> JK bi-LSTM), N=50000, K=16, C=128.
// Round 12: round-11 (2425us) + ldmatrix.x4 fragment loads in the fp16 GEMM
// (4x fewer shared-pipe ops in the mainloop). Math bit-identical.
// ---------------------------------------------------------------------------

#define NN 50000
#define KK 16
#define EE (NN * KK)
#define CC 128
#define JKH 192

#define BM 128
#define BN 128
#define BKT 32                      // halves per K-tile
#define RSTRH 40                    // halves per smem row (32 + 8 pad) = 80 B
#define TILE_B (BM * RSTRH * 2)     // 10240 bytes per tile side
#define STAGE_B (2 * TILE_B)        // 20480
#define SMEM_BYTES (3 * STAGE_B)    // 61440

// ---------------- static device scratch -------------------------------------
__device__ int    d_src[EE];
__device__ int    d_is64;
__device__ __half d_xh[NN * CC];
__device__ __half d_aggh[NN * CC];
__device__ __half d_xcath[3 * NN * CC];         // h1 | h2 | h3 (fp16)
__device__ __half d_hAh[NN * CC];
__device__ float  d_cA[NN * CC];
__device__ __half d_Pa[NN * 512];               // fp16 pre-activations
__device__ __half d_Pf[3 * NN * 768];
__device__ __half d_Pb[3 * NN * 768];
__device__ __half d_Z[NN * 768];
__device__ __half d_fwdh[3 * NN * JKH];
__device__ __half d_bwdph[3 * NN * JKH];
__device__ float  d_cF[NN * JKH];
__device__ float  d_cB[NN * JKH];
__device__ float  d_w[NN * 3];
__device__ __half d_wh[720896];                 // fp16 weights arena

__device__ __forceinline__ float sigmoidf_(float x) { return 1.f / (1.f + expf(-x)); }

// ---------------- edge-index probe + convert ---------------------------------
__global__ void detect_idx_kernel(const void* ei) {
    const long long* p = (const long long*)ei;
    int lane = threadIdx.x;
    int ok = 1;
#pragma unroll
    for (int i = 0; i < 4; ++i) {
        long long v = p[lane * 4 + i];
        if (v < 0 || v >= NN) ok = 0;
    }
    unsigned m = __ballot_sync(0xffffffffu, ok);
    if (lane == 0) d_is64 = (m == 0xffffffffu) ? 1 : 0;
}

__global__ void convert_src_kernel(const void* ei) {
    int idx = blockIdx.x * blockDim.x + threadIdx.x;
    if (idx >= EE) return;
    if (d_is64) d_src[idx] = (int)((const long long*)ei)[idx];
    else        d_src[idx] = ((const int*)ei)[idx];
}

// ---------------- fp32 -> fp16 conversion ------------------------------------
__global__ void cvt_half_kernel(const float* __restrict__ in, __half* __restrict__ out, int n4) {
    int i = blockIdx.x * blockDim.x + threadIdx.x;
    if (i >= n4) return;
    float4 v = ((const float4*)in)[i];
    ((__half2*)out)[i * 2]     = __floats2half2_rn(v.x, v.y);
    ((__half2*)out)[i * 2 + 1] = __floats2half2_rn(v.z, v.w);
}

#define NSEG 13
struct CvtJobs {
    const float* src[NSEG];
    __half*      dst[NSEG];
    int          end4[NSEG];
};

__global__ void cvt_half_multi_kernel(CvtJobs jobs, int total4) {
    int i = blockIdx.x * blockDim.x + threadIdx.x;
    if (i >= total4) return;
    int seg = 0;
#pragma unroll
    for (int s = 0; s < NSEG; ++s)
        if (i >= jobs.end4[s]) seg = s + 1;
    int base = (seg == 0) ? 0 : jobs.end4[seg - 1];
    int j = i - base;
    float4 v = ((const float4*)jobs.src[seg])[j];
    ((__half2*)jobs.dst[seg])[j * 2]     = __floats2half2_rn(v.x, v.y);
    ((__half2*)jobs.dst[seg])[j * 2 + 1] = __floats2half2_rn(v.z, v.w);
}

// ---------------- neighbor aggregations (half2) ------------------------------
__global__ void agg_mean_kernel(const __half* __restrict__ X, __half* __restrict__ out) {
    int idx = blockIdx.x * blockDim.x + threadIdx.x;
    if (idx >= NN * 64) return;
    int n = idx >> 6, c2 = idx & 63;
    const int* s = d_src + n * KK;
    float ax = 0.f, ay = 0.f;
#pragma unroll
    for (int j = 0; j < KK; ++j) {
        float2 v = __half22float2(*(const __half2*)(X + (size_t)s[j] * CC + 2 * c2));
        ax += v.x; ay += v.y;
    }
    ((__half2*)out)[idx] = __floats2half2_rn(ax * (1.f / 16.f), ay * (1.f / 16.f));
}

__global__ void agg_max_kernel(const __half* __restrict__ X, __half* __restrict__ out) {
    int idx = blockIdx.x * blockDim.x + threadIdx.x;
    if (idx >= NN * 64) return;
    int n = idx >> 6, c2 = idx & 63;
    const int* s = d_src + n * KK;
    float ax = -INFINITY, ay = -INFINITY;
#pragma unroll
    for (int j = 0; j < KK; ++j) {
        float2 v = __half22float2(*(const __half2*)(X + (size_t)s[j] * CC + 2 * c2));
        ax = fmaxf(ax, v.x); ay = fmaxf(ay, v.y);
    }
    ((__half2*)out)[idx] = __floats2half2_rn(ax, ay);
}

// ---------------- fp16 GEMM (cp.async 3-stage, m16n8k16, ldmatrix) ----------
__global__ __launch_bounds__(256, 2) void h16_gemm_kernel(
    const __half* __restrict__ A, const __half* __restrict__ B2,
    const __half* __restrict__ W1, const __half* __restrict__ W2,
    const float* __restrict__ bias,
    float* __restrict__ CoutF, __half* __restrict__ CoutH,
    int M, int Nc, int K1, int K2, int relu)
{
    extern __shared__ __align__(16) char smraw[];
    const int tid = threadIdx.x, wid = tid >> 5, lane = tid & 31;
    const int grp = lane >> 2, tig = lane & 3;
    const int warpM = wid >> 1, warpN = wid & 1;
    const int rowBase = blockIdx.x * BM, colBase = blockIdx.y * BN;
    const int Ktot = K1 + K2, nk = Ktot / BKT;
    const int cr = tid >> 2;               // row 0..63, +64 on second pass
    const int chh = (tid & 3) * 8;         // half offset within row

    // ldmatrix per-lane byte offsets within a tile
    const int sub = lane >> 3, r8 = lane & 7;
    uint32_t aoff[2], boff[4];
#pragma unroll
    for (int mt = 0; mt < 2; ++mt)
        aoff[mt] = ((warpM * 32 + mt * 16 + (sub & 1) * 8 + r8) * RSTRH
                    + (sub >> 1) * 8) * 2;
#pragma unroll
    for (int p = 0; p < 4; ++p)
        boff[p] = ((warpN * 64 + (2 * p + (sub >> 1)) * 8 + r8) * RSTRH
                   + (sub & 1) * 8) * 2;

    const uint32_t smBase32 = (uint32_t)__cvta_generic_to_shared(smraw);

    float c[2][8][4];
#pragma unroll
    for (int mt = 0; mt < 2; ++mt)
#pragma unroll
        for (int nt = 0; nt < 8; ++nt)
#pragma unroll
            for (int i = 0; i < 4; ++i) c[mt][nt][i] = 0.f;

    auto issue = [&](int it, int s) {
        if (it < nk) {
            int kk = it * BKT;
            const __half* asrc; const __half* wsrc; int ld, kb;
            if (kk < K1) { asrc = A;  wsrc = W1; ld = K1; kb = kk; }
            else         { asrc = B2; wsrc = W2; ld = K2; kb = kk - K1; }
            char* smA = smraw + s * STAGE_B;
            char* smB = smA + TILE_B;
#pragma unroll
            for (int p = 0; p < 2; ++p) {
                int r = cr + p * 64;
                int row = rowBase + r;
                int rc = (row < M) ? row : 0;
                uint32_t dst = (uint32_t)__cvta_generic_to_shared(smA + r * (RSTRH * 2) + chh * 2);
                const __half* g = asrc + (size_t)rc * ld + kb + chh;
                int sz = (row < M) ? 16 : 0;
                asm volatile("cp.async.cg.shared.global [%0], [%1], 16, %2;\n"
                             :: "r"(dst), "l"(g), "r"(sz));
            }
#pragma unroll
            for (int p = 0; p < 2; ++p) {
                int r = cr + p * 64;
                uint32_t dst = (uint32_t)__cvta_generic_to_shared(smB + r * (RSTRH * 2) + chh * 2);
                const __half* g = wsrc + (size_t)(colBase + r) * ld + kb + chh;
                asm volatile("cp.async.cg.shared.global [%0], [%1], 16;\n"
                             :: "r"(dst), "l"(g));
            }
        }
        asm volatile("cp.async.commit_group;\n");
    };

    issue(0, 0);
    issue(1, 1);

    for (int it = 0; it < nk; ++it) {
        asm volatile("cp.async.wait_group 1;\n");
        __syncthreads();
        const int s = it % 3;
        const uint32_t smA32 = smBase32 + s * STAGE_B;
        const uint32_t smB32 = smA32 + TILE_B;
#pragma unroll
        for (int kt = 0; kt < 2; ++kt) {
            const uint32_t kbyte = kt * 32;
            uint32_t af[2][4], bf[8][2];
#pragma unroll
            for (int mt = 0; mt < 2; ++mt) {
                asm volatile(
                    "ldmatrix.sync.aligned.m8n8.x4.shared.b16 {%0,%1,%2,%3}, [%4];\n"
                    : "=r"(af[mt][0]), "=r"(af[mt][1]), "=r"(af[mt][2]), "=r"(af[mt][3])
                    : "r"(smA32 + aoff[mt] + kbyte));
            }
#pragma unroll
            for (int p = 0; p < 4; ++p) {
                asm volatile(
                    "ldmatrix.sync.aligned.m8n8.x4.shared.b16 {%0,%1,%2,%3}, [%4];\n"
                    : "=r"(bf[2 * p][0]), "=r"(bf[2 * p][1]),
                      "=r"(bf[2 * p + 1][0]), "=r"(bf[2 * p + 1][1])
                    : "r"(smB32 + boff[p] + kbyte));
            }
#pragma unroll
            for (int mt = 0; mt < 2; ++mt)
#pragma unroll
                for (int nt = 0; nt < 8; ++nt) {
                    asm volatile(
                        "mma.sync.aligned.m16n8k16.row.col.f32.f16.f16.f32 "
                        "{%0,%1,%2,%3}, {%4,%5,%6,%7}, {%8,%9}, {%0,%1,%2,%3};\n"
                        : "+f"(c[mt][nt][0]), "+f"(c[mt][nt][1]),
                          "+f"(c[mt][nt][2]), "+f"(c[mt][nt][3])
                        : "r"(af[mt][0]), "r"(af[mt][1]), "r"(af[mt][2]), "r"(af[mt][3]),
                          "r"(bf[nt][0]), "r"(bf[nt][1]));
                }
        }
        issue(it + 2, (it + 2) % 3);
    }

#pragma unroll
    for (int mt = 0; mt < 2; ++mt) {
#pragma unroll
        for (int nt = 0; nt < 8; ++nt) {
            int col = colBase + warpN * 64 + nt * 8 + tig * 2;
            float b0 = bias ? bias[col] : 0.f;
            float b1 = bias ? bias[col + 1] : 0.f;
            int r0 = rowBase + warpM * 32 + mt * 16 + grp;
            int r1 = r0 + 8;
            float v0 = c[mt][nt][0] + b0, v1 = c[mt][nt][1] + b1;
            float v2 = c[mt][nt][2] + b0, v3 = c[mt][nt][3] + b1;
            if (relu) { v0 = fmaxf(v0, 0.f); v1 = fmaxf(v1, 0.f);
                        v2 = fmaxf(v2, 0.f); v3 = fmaxf(v3, 0.f); }
            if (CoutF) {
                if (r0 < M) *(float2*)(CoutF + (size_t)r0 * Nc + col) = make_float2(v0, v1);
                if (r1 < M) *(float2*)(CoutF + (size_t)r1 * Nc + col) = make_float2(v2, v3);
            } else {
                if (r0 < M) *(__half2*)(CoutH + (size_t)r0 * Nc + col) = __floats2half2_rn(v0, v1);
                if (r1 < M) *(__half2*)(CoutH + (size_t)r1 * Nc + col) = __floats2half2_rn(v2, v3);
            }
        }
    }
}

// ---------------- LSTM gates: z = Zrec + P[gathered] + biases ----------------
__global__ void lstm_gates_kernel(
    const __half* __restrict__ Zrec,
    const __half* __restrict__ P,
    const int* __restrict__ src, int t,
    const float* __restrict__ bih, const float* __restrict__ bhh,
    __half* __restrict__ h_out, float* __restrict__ c_st,
    int H, int first)
{
    int hv = H >> 2;
    int idx = blockIdx.x * blockDim.x + threadIdx.x;
    if (idx >= NN * hv) return;
    int n = idx / hv, q = idx - n * hv;
    int pn = src ? src[n * KK + t] : n;
    const uint2* pr = (const uint2*)(P + (size_t)pn * 4 * H);
    const uint2* zr = Zrec ? (const uint2*)(Zrec + (size_t)n * 4 * H) : nullptr;
    const float4* b1 = (const float4*)bih;
    const float4* b2 = (const float4*)bhh;

    float4 z[4];
#pragma unroll
    for (int g = 0; g < 4; ++g) {
        uint2 pu = pr[g * hv + q];
        float2 pa = __half22float2(*(const __half2*)&pu.x);
        float2 pb = __half22float2(*(const __half2*)&pu.y);
        float4 a = b1[g * hv + q], b = b2[g * hv + q];
        float4 v = make_float4(pa.x + a.x + b.x, pa.y + a.y + b.y,
                               pb.x + a.z + b.z, pb.y + a.w + b.w);
        if (zr) {
            uint2 zu = zr[g * hv + q];
            float2 za = __half22float2(*(const __half2*)&zu.x);
            float2 zb = __half22float2(*(const __half2*)&zu.y);
            v.x += za.x; v.y += za.y; v.z += zb.x; v.w += zb.y;
        }
        z[g] = v;
    }
    float4 cold = first ? make_float4(0.f, 0.f, 0.f, 0.f) : ((float4*)c_st)[idx];
    float4 cn;
    float hv4[4];
#pragma unroll
    for (int e = 0; e < 4; ++e) {
        float zi = (&z[0].x)[e], zf = (&z[1].x)[e], zg = (&z[2].x)[e], zo = (&z[3].x)[e];
        float ig = sigmoidf_(zi), fg = sigmoidf_(zf);
        float gg = tanhf(zg), og = sigmoidf_(zo);
        float cc = fg * (&cold.x)[e] + ig * gg;
        (&cn.x)[e] = cc;
        hv4[e] = og * tanhf(cc);
    }
    ((float4*)c_st)[idx] = cn;
    ((__half2*)h_out)[idx * 2]     = __floats2half2_rn(hv4[0], hv4[1]);
    ((__half2*)h_out)[idx * 2 + 1] = __floats2half2_rn(hv4[2], hv4[3]);
}

// ---------------- JK attention scores + softmax ------------------------------
__global__ void jk_score_kernel(const float* __restrict__ attw,
                                const float* __restrict__ attb,
                                float* __restrict__ wout)
{
    int gtid = blockIdx.x * blockDim.x + threadIdx.x;
    int node = gtid >> 5;
    int lane = gtid & 31;
    if (node >= NN) return;
    float sc[3];
#pragma unroll
    for (int t = 0; t < 3; ++t) {
        const __half* f = d_fwdh  + (size_t)t * NN * JKH + (size_t)node * JKH;
        const __half* b = d_bwdph + (size_t)t * NN * JKH + (size_t)node * JKH;
        float s = 0.f;
        for (int k = lane; k < JKH; k += 32)
            s += __half2float(f[k]) * attw[k] + __half2float(b[k]) * attw[JKH + k];
#pragma unroll
        for (int off = 16; off > 0; off >>= 1)
            s += __shfl_xor_sync(0xffffffffu, s, off);
        sc[t] = s + attb[0];
    }
    if (lane == 0) {
        float m = fmaxf(sc[0], fmaxf(sc[1], sc[2]));
        float e0 = expf(sc[0] - m), e1 = expf(sc[1] - m), e2 = expf(sc[2] - m);
        float inv = 1.f / (e0 + e1 + e2);
        wout[node * 3 + 0] = e0 * inv;
        wout[node * 3 + 1] = e1 * inv;
        wout[node * 3 + 2] = e2 * inv;
    }
}

__global__ void jk_combine_kernel(float* __restrict__ out) {
    int idx = blockIdx.x * blockDim.x + threadIdx.x;
    if (idx >= NN * 64) return;
    int n = idx >> 6;
    float w0 = d_w[n * 3 + 0], w1 = d_w[n * 3 + 1], w2 = d_w[n * 3 + 2];
    float2 a = __half22float2(((const __half2*)d_xcath)[idx]);
    float2 b = __half22float2(((const __half2*)(d_xcath + NN * CC))[idx]);
    float2 c = __half22float2(((const __half2*)(d_xcath + 2 * NN * CC))[idx]);
    ((float2*)out)[idx] = make_float2(w0 * a.x + w1 * b.x + w2 * c.x,
                                      w0 * a.y + w1 * b.y + w2 * c.y);
}

// ---------------------------------------------------------------------------
static inline int cdiv(int a, int b) { return (a + b - 1) / b; }

extern "C" void kernel_launch(void* const* d_in, const int* in_sizes, int n_in,
                              void* d_out, int out_size)
{
    const void* ei = nullptr;
    const float* x = nullptr;
    const float* wp[23];
    int wcount = 0;
    for (int i = 0; i < n_in; ++i) {
        if (in_sizes[i] == 2 * EE)       ei = d_in[i];
        else if (in_sizes[i] == NN * CC) x  = (const float*)d_in[i];
        else if (wcount < 23)            wp[wcount++] = (const float*)d_in[i];
    }
    const float *Wl1 = wp[0],  *bl1 = wp[1],  *Wr1 = wp[2];
    const float *Wl2 = wp[3],  *bl2 = wp[4],  *Wr2 = wp[5];
    const float *Wl3 = wp[6],  *bl3 = wp[7],  *Wr3 = wp[8];
    const float *Wih_a = wp[9],  *Whh_a = wp[10], *bih_a = wp[11], *bhh_a = wp[12];
    const float *Wih_f = wp[13], *Whh_f = wp[14], *bih_f = wp[15], *bhh_f = wp[16];
    const float *Wih_b = wp[17], *Whh_b = wp[18], *bih_b = wp[19], *bhh_b = wp[20];
    const float *att_w = wp[21], *att_b = wp[22];

    __half *xh, *aggh, *xcath, *hAh, *fwdh, *bwdph, *wh, *Pa, *Pf, *Pb, *Z;
    float *cA, *cF, *cB, *wbuf;
    int* srcp;
    cudaGetSymbolAddress((void**)&srcp,  d_src);
    cudaGetSymbolAddress((void**)&xh,    d_xh);
    cudaGetSymbolAddress((void**)&aggh,  d_aggh);
    cudaGetSymbolAddress((void**)&xcath, d_xcath);
    cudaGetSymbolAddress((void**)&hAh,   d_hAh);
    cudaGetSymbolAddress((void**)&cA,    d_cA);
    cudaGetSymbolAddress((void**)&Pa,    d_Pa);
    cudaGetSymbolAddress((void**)&Pf,    d_Pf);
    cudaGetSymbolAddress((void**)&Pb,    d_Pb);
    cudaGetSymbolAddress((void**)&Z,     d_Z);
    cudaGetSymbolAddress((void**)&fwdh,  d_fwdh);
    cudaGetSymbolAddress((void**)&bwdph, d_bwdph);
    cudaGetSymbolAddress((void**)&cF,    d_cF);
    cudaGetSymbolAddress((void**)&cB,    d_cB);
    cudaGetSymbolAddress((void**)&wbuf,  d_w);
    cudaGetSymbolAddress((void**)&wh,    d_wh);

    __half* hWl1 = wh;                 __half* hWr1 = hWl1 + 16384;
    __half* hWl2 = hWr1 + 16384;       __half* hWr2 = hWl2 + 16384;
    __half* hWl3 = hWr2 + 16384;       __half* hWr3 = hWl3 + 16384;
    __half* hWih_a = hWr3 + 16384;     __half* hWhh_a = hWih_a + 65536;
    __half* hWih_f = hWhh_a + 65536;   __half* hWhh_f = hWih_f + 98304;
    __half* hWih_b = hWhh_f + 147456;  __half* hWhh_b = hWih_b + 98304;

    __half* h1h = xcath;
    __half* h2h = xcath + NN * CC;
    __half* h3h = xcath + 2 * NN * CC;
    float* out = (float*)d_out;

    cudaFuncSetAttribute(h16_gemm_kernel,
                         cudaFuncAttributeMaxDynamicSharedMemorySize, SMEM_BYTES);

    const int NH2_BLK = cdiv(NN * 64, 256);
    const int NC_BLK4 = cdiv(NN * CC / 4, 256);
    const int NJ_BLK4 = cdiv(NN * JKH / 4, 256);
    dim3 g128(cdiv(NN, BM), 1);
    dim3 g512(cdiv(NN, BM), 4);
    dim3 g768(cdiv(NN, BM), 6);
    dim3 g768x3(cdiv(3 * NN, BM), 6);

    // ---- prep: edge index + fp16 conversion (batched weights, 1 launch)
    detect_idx_kernel<<<1, 32>>>(ei);
    convert_src_kernel<<<cdiv(EE, 256), 256>>>(ei);
    cvt_half_kernel<<<cdiv(NN * CC / 4, 256), 256>>>(x, xh, NN * CC / 4);

    {
        CvtJobs jobs;
        const float* srcs[NSEG] = {Wl1, Wr1, Wl2, Wr2, Wl3, Wr3,
                                   Wih_a, Whh_a, Wih_f, Whh_f, Wih_b, Whh_b, nullptr};
        __half* dsts[NSEG] = {hWl1, hWr1, hWl2, hWr2, hWl3, hWr3,
                              hWih_a, hWhh_a, hWih_f, hWhh_f, hWih_b, hWhh_b, nullptr};
        int n4s[NSEG] = {4096, 4096, 4096, 4096, 4096, 4096,
                         16384, 16384, 24576, 36864, 24576, 36864, 0};
        int acc = 0;
        for (int s = 0; s < NSEG; ++s) {
            jobs.src[s] = srcs[s] ? srcs[s] : Wl1;
            jobs.dst[s] = dsts[s] ? dsts[s] : hWl1;
            acc += n4s[s];
            jobs.end4[s] = acc;
        }
        cvt_half_multi_kernel<<<cdiv(acc, 256), 256>>>(jobs, acc);
    }

    // ---- layer 1: mean SAGE + relu -> h1 (fp16)
    agg_mean_kernel<<<NH2_BLK, 256>>>(xh, aggh);
    h16_gemm_kernel<<<g128, 256, SMEM_BYTES>>>(aggh, xh, hWl1, hWr1, bl1,
                                               nullptr, h1h, NN, 128, 128, 128, 1);

    // ---- layer 2: max SAGE + relu -> h2 (fp16)
    agg_max_kernel<<<NH2_BLK, 256>>>(h1h, aggh);
    h16_gemm_kernel<<<g128, 256, SMEM_BYTES>>>(aggh, h1h, hWl2, hWr2, bl2,
                                               nullptr, h2h, NN, 128, 128, 128, 1);

    // ---- layer 3: LSTM aggregation (hoisted input projection, fp16 P/Z)
    h16_gemm_kernel<<<g512, 256, SMEM_BYTES>>>(h2h, nullptr, hWih_a, nullptr, nullptr,
                                               nullptr, Pa, NN, 512, 128, 0, 0);
    for (int t = 0; t < KK; ++t) {
        const __half* zr = nullptr;
        if (t > 0) {
            h16_gemm_kernel<<<g512, 256, SMEM_BYTES>>>(hAh, nullptr, hWhh_a, nullptr, nullptr,
                                                       nullptr, Z, NN, 512, 128, 0, 0);
            zr = Z;
        }
        lstm_gates_kernel<<<NC_BLK4, 256>>>(zr, Pa, srcp, t, bih_a, bhh_a,
                                            hAh, cA, 128, t == 0);
    }
    h16_gemm_kernel<<<g128, 256, SMEM_BYTES>>>(hAh, h2h, hWl3, hWr3, bl3,
                                               nullptr, h3h, NN, 128, 128, 128, 0);

    // ---- JK bi-LSTM: batched input projections (fp16 P)
    h16_gemm_kernel<<<g768x3, 256, SMEM_BYTES>>>(xcath, nullptr, hWih_f, nullptr, nullptr,
                                                 nullptr, Pf, 3 * NN, 768, 128, 0, 0);
    h16_gemm_kernel<<<g768x3, 256, SMEM_BYTES>>>(xcath, nullptr, hWih_b, nullptr, nullptr,
                                                 nullptr, Pb, 3 * NN, 768, 128, 0, 0);

    for (int t = 0; t < 3; ++t) {
        const __half* zrF = nullptr;
        if (t > 0) {
            h16_gemm_kernel<<<g768, 256, SMEM_BYTES>>>(
                fwdh + (size_t)(t - 1) * NN * JKH, nullptr, hWhh_f, nullptr, nullptr,
                nullptr, Z, NN, 768, JKH, 0, 0);
            zrF = Z;
        }
        lstm_gates_kernel<<<NJ_BLK4, 256>>>(zrF, Pf + (size_t)t * NN * 768, nullptr, 0,
                                            bih_f, bhh_f,
                                            fwdh + (size_t)t * NN * JKH, cF, JKH, t == 0);
        const __half* zrB = nullptr;
        if (t > 0) {
            h16_gemm_kernel<<<g768, 256, SMEM_BYTES>>>(
                bwdph + (size_t)(3 - t) * NN * JKH, nullptr, hWhh_b, nullptr, nullptr,
                nullptr, Z, NN, 768, JKH, 0, 0);
            zrB = Z;
        }
        lstm_gates_kernel<<<NJ_BLK4, 256>>>(zrB, Pb + (size_t)(2 - t) * NN * 768, nullptr, 0,
                                            bih_b, bhh_b,
                                            bwdph + (size_t)(2 - t) * NN * JKH, cB, JKH, t == 0);
    }

    // ---- attention + combine
    jk_score_kernel<<<cdiv(NN * 32, 256), 256>>>(att_w, att_b, wbuf);
    jk_combine_kernel<<<NH2_BLK, 256>>>(out);

    (void)out_size;
}

// round 13
// speedup vs baseline: 2.2233x; 1.0694x over previous
#include <cuda_runtime.h>
#include <cuda_fp16.h>
#include <math.h>
#include <stdint.h>

// ---------------------------------------------------------------------------
// GraphSAGE (mean -> max -> lstm aggr -> JK bi-LSTM), N=50000, K=16, C=128.
// Round 13: round-12 (2363us) + tanh.approx gate nonlinearities
// (sigmoid via 0.5+0.5*tanh(x/2)). Everything else unchanged.
// ---------------------------------------------------------------------------

#define NN 50000
#define KK 16
#define EE (NN * KK)
#define CC 128
#define JKH 192

#define BM 128
#define BN 128
#define BKT 32                      // halves per K-tile
#define RSTRH 40                    // halves per smem row (32 + 8 pad) = 80 B
#define TILE_B (BM * RSTRH * 2)     // 10240 bytes per tile side
#define STAGE_B (2 * TILE_B)        // 20480
#define SMEM_BYTES (3 * STAGE_B)    // 61440

// ---------------- static device scratch -------------------------------------
__device__ int    d_src[EE];
__device__ int    d_is64;
__device__ __half d_xh[NN * CC];
__device__ __half d_aggh[NN * CC];
__device__ __half d_xcath[3 * NN * CC];         // h1 | h2 | h3 (fp16)
__device__ __half d_hAh[NN * CC];
__device__ float  d_cA[NN * CC];
__device__ __half d_Pa[NN * 512];               // fp16 pre-activations
__device__ __half d_Pf[3 * NN * 768];
__device__ __half d_Pb[3 * NN * 768];
__device__ __half d_Z[NN * 768];
__device__ __half d_fwdh[3 * NN * JKH];
__device__ __half d_bwdph[3 * NN * JKH];
__device__ float  d_cF[NN * JKH];
__device__ float  d_cB[NN * JKH];
__device__ float  d_w[NN * 3];
__device__ __half d_wh[720896];                 // fp16 weights arena

// fast gate nonlinearities: tanh.approx (1 MUFU op), sigmoid via tanh
__device__ __forceinline__ float tanh_fast(float x) {
    float y;
    asm("tanh.approx.f32 %0, %1;" : "=f"(y) : "f"(x));
    return y;
}
__device__ __forceinline__ float sigmoid_fast(float x) {
    return fmaf(tanh_fast(0.5f * x), 0.5f, 0.5f);
}

// ---------------- edge-index probe + convert ---------------------------------
__global__ void detect_idx_kernel(const void* ei) {
    const long long* p = (const long long*)ei;
    int lane = threadIdx.x;
    int ok = 1;
#pragma unroll
    for (int i = 0; i < 4; ++i) {
        long long v = p[lane * 4 + i];
        if (v < 0 || v >= NN) ok = 0;
    }
    unsigned m = __ballot_sync(0xffffffffu, ok);
    if (lane == 0) d_is64 = (m == 0xffffffffu) ? 1 : 0;
}

__global__ void convert_src_kernel(const void* ei) {
    int idx = blockIdx.x * blockDim.x + threadIdx.x;
    if (idx >= EE) return;
    if (d_is64) d_src[idx] = (int)((const long long*)ei)[idx];
    else        d_src[idx] = ((const int*)ei)[idx];
}

// ---------------- fp32 -> fp16 conversion ------------------------------------
__global__ void cvt_half_kernel(const float* __restrict__ in, __half* __restrict__ out, int n4) {
    int i = blockIdx.x * blockDim.x + threadIdx.x;
    if (i >= n4) return;
    float4 v = ((const float4*)in)[i];
    ((__half2*)out)[i * 2]     = __floats2half2_rn(v.x, v.y);
    ((__half2*)out)[i * 2 + 1] = __floats2half2_rn(v.z, v.w);
}

#define NSEG 13
struct CvtJobs {
    const float* src[NSEG];
    __half*      dst[NSEG];
    int          end4[NSEG];
};

__global__ void cvt_half_multi_kernel(CvtJobs jobs, int total4) {
    int i = blockIdx.x * blockDim.x + threadIdx.x;
    if (i >= total4) return;
    int seg = 0;
#pragma unroll
    for (int s = 0; s < NSEG; ++s)
        if (i >= jobs.end4[s]) seg = s + 1;
    int base = (seg == 0) ? 0 : jobs.end4[seg - 1];
    int j = i - base;
    float4 v = ((const float4*)jobs.src[seg])[j];
    ((__half2*)jobs.dst[seg])[j * 2]     = __floats2half2_rn(v.x, v.y);
    ((__half2*)jobs.dst[seg])[j * 2 + 1] = __floats2half2_rn(v.z, v.w);
}

// ---------------- neighbor aggregations (half2) ------------------------------
__global__ void agg_mean_kernel(const __half* __restrict__ X, __half* __restrict__ out) {
    int idx = blockIdx.x * blockDim.x + threadIdx.x;
    if (idx >= NN * 64) return;
    int n = idx >> 6, c2 = idx & 63;
    const int* s = d_src + n * KK;
    float ax = 0.f, ay = 0.f;
#pragma unroll
    for (int j = 0; j < KK; ++j) {
        float2 v = __half22float2(*(const __half2*)(X + (size_t)s[j] * CC + 2 * c2));
        ax += v.x; ay += v.y;
    }
    ((__half2*)out)[idx] = __floats2half2_rn(ax * (1.f / 16.f), ay * (1.f / 16.f));
}

__global__ void agg_max_kernel(const __half* __restrict__ X, __half* __restrict__ out) {
    int idx = blockIdx.x * blockDim.x + threadIdx.x;
    if (idx >= NN * 64) return;
    int n = idx >> 6, c2 = idx & 63;
    const int* s = d_src + n * KK;
    float ax = -INFINITY, ay = -INFINITY;
#pragma unroll
    for (int j = 0; j < KK; ++j) {
        float2 v = __half22float2(*(const __half2*)(X + (size_t)s[j] * CC + 2 * c2));
        ax = fmaxf(ax, v.x); ay = fmaxf(ay, v.y);
    }
    ((__half2*)out)[idx] = __floats2half2_rn(ax, ay);
}

// ---------------- fp16 GEMM (cp.async 3-stage, m16n8k16, ldmatrix) ----------
__global__ __launch_bounds__(256, 2) void h16_gemm_kernel(
    const __half* __restrict__ A, const __half* __restrict__ B2,
    const __half* __restrict__ W1, const __half* __restrict__ W2,
    const float* __restrict__ bias,
    float* __restrict__ CoutF, __half* __restrict__ CoutH,
    int M, int Nc, int K1, int K2, int relu)
{
    extern __shared__ __align__(16) char smraw[];
    const int tid = threadIdx.x, wid = tid >> 5, lane = tid & 31;
    const int grp = lane >> 2, tig = lane & 3;
    const int warpM = wid >> 1, warpN = wid & 1;
    const int rowBase = blockIdx.x * BM, colBase = blockIdx.y * BN;
    const int Ktot = K1 + K2, nk = Ktot / BKT;
    const int cr = tid >> 2;               // row 0..63, +64 on second pass
    const int chh = (tid & 3) * 8;         // half offset within row

    // ldmatrix per-lane byte offsets within a tile
    const int sub = lane >> 3, r8 = lane & 7;
    uint32_t aoff[2], boff[4];
#pragma unroll
    for (int mt = 0; mt < 2; ++mt)
        aoff[mt] = ((warpM * 32 + mt * 16 + (sub & 1) * 8 + r8) * RSTRH
                    + (sub >> 1) * 8) * 2;
#pragma unroll
    for (int p = 0; p < 4; ++p)
        boff[p] = ((warpN * 64 + (2 * p + (sub >> 1)) * 8 + r8) * RSTRH
                   + (sub & 1) * 8) * 2;

    const uint32_t smBase32 = (uint32_t)__cvta_generic_to_shared(smraw);

    float c[2][8][4];
#pragma unroll
    for (int mt = 0; mt < 2; ++mt)
#pragma unroll
        for (int nt = 0; nt < 8; ++nt)
#pragma unroll
            for (int i = 0; i < 4; ++i) c[mt][nt][i] = 0.f;

    auto issue = [&](int it, int s) {
        if (it < nk) {
            int kk = it * BKT;
            const __half* asrc; const __half* wsrc; int ld, kb;
            if (kk < K1) { asrc = A;  wsrc = W1; ld = K1; kb = kk; }
            else         { asrc = B2; wsrc = W2; ld = K2; kb = kk - K1; }
            char* smA = smraw + s * STAGE_B;
            char* smB = smA + TILE_B;
#pragma unroll
            for (int p = 0; p < 2; ++p) {
                int r = cr + p * 64;
                int row = rowBase + r;
                int rc = (row < M) ? row : 0;
                uint32_t dst = (uint32_t)__cvta_generic_to_shared(smA + r * (RSTRH * 2) + chh * 2);
                const __half* g = asrc + (size_t)rc * ld + kb + chh;
                int sz = (row < M) ? 16 : 0;
                asm volatile("cp.async.cg.shared.global [%0], [%1], 16, %2;\n"
                             :: "r"(dst), "l"(g), "r"(sz));
            }
#pragma unroll
            for (int p = 0; p < 2; ++p) {
                int r = cr + p * 64;
                uint32_t dst = (uint32_t)__cvta_generic_to_shared(smB + r * (RSTRH * 2) + chh * 2);
                const __half* g = wsrc + (size_t)(colBase + r) * ld + kb + chh;
                asm volatile("cp.async.cg.shared.global [%0], [%1], 16;\n"
                             :: "r"(dst), "l"(g));
            }
        }
        asm volatile("cp.async.commit_group;\n");
    };

    issue(0, 0);
    issue(1, 1);

    for (int it = 0; it < nk; ++it) {
        asm volatile("cp.async.wait_group 1;\n");
        __syncthreads();
        const int s = it % 3;
        const uint32_t smA32 = smBase32 + s * STAGE_B;
        const uint32_t smB32 = smA32 + TILE_B;
#pragma unroll
        for (int kt = 0; kt < 2; ++kt) {
            const uint32_t kbyte = kt * 32;
            uint32_t af[2][4], bf[8][2];
#pragma unroll
            for (int mt = 0; mt < 2; ++mt) {
                asm volatile(
                    "ldmatrix.sync.aligned.m8n8.x4.shared.b16 {%0,%1,%2,%3}, [%4];\n"
                    : "=r"(af[mt][0]), "=r"(af[mt][1]), "=r"(af[mt][2]), "=r"(af[mt][3])
                    : "r"(smA32 + aoff[mt] + kbyte));
            }
#pragma unroll
            for (int p = 0; p < 4; ++p) {
                asm volatile(
                    "ldmatrix.sync.aligned.m8n8.x4.shared.b16 {%0,%1,%2,%3}, [%4];\n"
                    : "=r"(bf[2 * p][0]), "=r"(bf[2 * p][1]),
                      "=r"(bf[2 * p + 1][0]), "=r"(bf[2 * p + 1][1])
                    : "r"(smB32 + boff[p] + kbyte));
            }
#pragma unroll
            for (int mt = 0; mt < 2; ++mt)
#pragma unroll
                for (int nt = 0; nt < 8; ++nt) {
                    asm volatile(
                        "mma.sync.aligned.m16n8k16.row.col.f32.f16.f16.f32 "
                        "{%0,%1,%2,%3}, {%4,%5,%6,%7}, {%8,%9}, {%0,%1,%2,%3};\n"
                        : "+f"(c[mt][nt][0]), "+f"(c[mt][nt][1]),
                          "+f"(c[mt][nt][2]), "+f"(c[mt][nt][3])
                        : "r"(af[mt][0]), "r"(af[mt][1]), "r"(af[mt][2]), "r"(af[mt][3]),
                          "r"(bf[nt][0]), "r"(bf[nt][1]));
                }
        }
        issue(it + 2, (it + 2) % 3);
    }

#pragma unroll
    for (int mt = 0; mt < 2; ++mt) {
#pragma unroll
        for (int nt = 0; nt < 8; ++nt) {
            int col = colBase + warpN * 64 + nt * 8 + tig * 2;
            float b0 = bias ? bias[col] : 0.f;
            float b1 = bias ? bias[col + 1] : 0.f;
            int r0 = rowBase + warpM * 32 + mt * 16 + grp;
            int r1 = r0 + 8;
            float v0 = c[mt][nt][0] + b0, v1 = c[mt][nt][1] + b1;
            float v2 = c[mt][nt][2] + b0, v3 = c[mt][nt][3] + b1;
            if (relu) { v0 = fmaxf(v0, 0.f); v1 = fmaxf(v1, 0.f);
                        v2 = fmaxf(v2, 0.f); v3 = fmaxf(v3, 0.f); }
            if (CoutF) {
                if (r0 < M) *(float2*)(CoutF + (size_t)r0 * Nc + col) = make_float2(v0, v1);
                if (r1 < M) *(float2*)(CoutF + (size_t)r1 * Nc + col) = make_float2(v2, v3);
            } else {
                if (r0 < M) *(__half2*)(CoutH + (size_t)r0 * Nc + col) = __floats2half2_rn(v0, v1);
                if (r1 < M) *(__half2*)(CoutH + (size_t)r1 * Nc + col) = __floats2half2_rn(v2, v3);
            }
        }
    }
}

// ---------------- LSTM gates: z = Zrec + P[gathered] + biases ----------------
// P/Zrec fp16; biases fp32; h_out fp16; c_st fp32. Fast tanh.approx gates.
__global__ void lstm_gates_kernel(
    const __half* __restrict__ Zrec,
    const __half* __restrict__ P,
    const int* __restrict__ src, int t,
    const float* __restrict__ bih, const float* __restrict__ bhh,
    __half* __restrict__ h_out, float* __restrict__ c_st,
    int H, int first)
{
    int hv = H >> 2;
    int idx = blockIdx.x * blockDim.x + threadIdx.x;
    if (idx >= NN * hv) return;
    int n = idx / hv, q = idx - n * hv;
    int pn = src ? src[n * KK + t] : n;
    const uint2* pr = (const uint2*)(P + (size_t)pn * 4 * H);
    const uint2* zr = Zrec ? (const uint2*)(Zrec + (size_t)n * 4 * H) : nullptr;
    const float4* b1 = (const float4*)bih;
    const float4* b2 = (const float4*)bhh;

    float4 z[4];
#pragma unroll
    for (int g = 0; g < 4; ++g) {
        uint2 pu = pr[g * hv + q];
        float2 pa = __half22float2(*(const __half2*)&pu.x);
        float2 pb = __half22float2(*(const __half2*)&pu.y);
        float4 a = b1[g * hv + q], b = b2[g * hv + q];
        float4 v = make_float4(pa.x + a.x + b.x, pa.y + a.y + b.y,
                               pb.x + a.z + b.z, pb.y + a.w + b.w);
        if (zr) {
            uint2 zu = zr[g * hv + q];
            float2 za = __half22float2(*(const __half2*)&zu.x);
            float2 zb = __half22float2(*(const __half2*)&zu.y);
            v.x += za.x; v.y += za.y; v.z += zb.x; v.w += zb.y;
        }
        z[g] = v;
    }
    float4 cold = first ? make_float4(0.f, 0.f, 0.f, 0.f) : ((float4*)c_st)[idx];
    float4 cn;
    float hv4[4];
#pragma unroll
    for (int e = 0; e < 4; ++e) {
        float zi = (&z[0].x)[e], zf = (&z[1].x)[e], zg = (&z[2].x)[e], zo = (&z[3].x)[e];
        float ig = sigmoid_fast(zi), fg = sigmoid_fast(zf);
        float gg = tanh_fast(zg), og = sigmoid_fast(zo);
        float cc = fg * (&cold.x)[e] + ig * gg;
        (&cn.x)[e] = cc;
        hv4[e] = og * tanh_fast(cc);
    }
    ((float4*)c_st)[idx] = cn;
    ((__half2*)h_out)[idx * 2]     = __floats2half2_rn(hv4[0], hv4[1]);
    ((__half2*)h_out)[idx * 2 + 1] = __floats2half2_rn(hv4[2], hv4[3]);
}

// ---------------- JK attention scores + softmax (precise math) ---------------
__global__ void jk_score_kernel(const float* __restrict__ attw,
                                const float* __restrict__ attb,
                                float* __restrict__ wout)
{
    int gtid = blockIdx.x * blockDim.x + threadIdx.x;
    int node = gtid >> 5;
    int lane = gtid & 31;
    if (node >= NN) return;
    float sc[3];
#pragma unroll
    for (int t = 0; t < 3; ++t) {
        const __half* f = d_fwdh  + (size_t)t * NN * JKH + (size_t)node * JKH;
        const __half* b = d_bwdph + (size_t)t * NN * JKH + (size_t)node * JKH;
        float s = 0.f;
        for (int k = lane; k < JKH; k += 32)
            s += __half2float(f[k]) * attw[k] + __half2float(b[k]) * attw[JKH + k];
#pragma unroll
        for (int off = 16; off > 0; off >>= 1)
            s += __shfl_xor_sync(0xffffffffu, s, off);
        sc[t] = s + attb[0];
    }
    if (lane == 0) {
        float m = fmaxf(sc[0], fmaxf(sc[1], sc[2]));
        float e0 = expf(sc[0] - m), e1 = expf(sc[1] - m), e2 = expf(sc[2] - m);
        float inv = 1.f / (e0 + e1 + e2);
        wout[node * 3 + 0] = e0 * inv;
        wout[node * 3 + 1] = e1 * inv;
        wout[node * 3 + 2] = e2 * inv;
    }
}

__global__ void jk_combine_kernel(float* __restrict__ out) {
    int idx = blockIdx.x * blockDim.x + threadIdx.x;
    if (idx >= NN * 64) return;
    int n = idx >> 6;
    float w0 = d_w[n * 3 + 0], w1 = d_w[n * 3 + 1], w2 = d_w[n * 3 + 2];
    float2 a = __half22float2(((const __half2*)d_xcath)[idx]);
    float2 b = __half22float2(((const __half2*)(d_xcath + NN * CC))[idx]);
    float2 c = __half22float2(((const __half2*)(d_xcath + 2 * NN * CC))[idx]);
    ((float2*)out)[idx] = make_float2(w0 * a.x + w1 * b.x + w2 * c.x,
                                      w0 * a.y + w1 * b.y + w2 * c.y);
}

// ---------------------------------------------------------------------------
static inline int cdiv(int a, int b) { return (a + b - 1) / b; }

extern "C" void kernel_launch(void* const* d_in, const int* in_sizes, int n_in,
                              void* d_out, int out_size)
{
    const void* ei = nullptr;
    const float* x = nullptr;
    const float* wp[23];
    int wcount = 0;
    for (int i = 0; i < n_in; ++i) {
        if (in_sizes[i] == 2 * EE)       ei = d_in[i];
        else if (in_sizes[i] == NN * CC) x  = (const float*)d_in[i];
        else if (wcount < 23)            wp[wcount++] = (const float*)d_in[i];
    }
    const float *Wl1 = wp[0],  *bl1 = wp[1],  *Wr1 = wp[2];
    const float *Wl2 = wp[3],  *bl2 = wp[4],  *Wr2 = wp[5];
    const float *Wl3 = wp[6],  *bl3 = wp[7],  *Wr3 = wp[8];
    const float *Wih_a = wp[9],  *Whh_a = wp[10], *bih_a = wp[11], *bhh_a = wp[12];
    const float *Wih_f = wp[13], *Whh_f = wp[14], *bih_f = wp[15], *bhh_f = wp[16];
    const float *Wih_b = wp[17], *Whh_b = wp[18], *bih_b = wp[19], *bhh_b = wp[20];
    const float *att_w = wp[21], *att_b = wp[22];

    __half *xh, *aggh, *xcath, *hAh, *fwdh, *bwdph, *wh, *Pa, *Pf, *Pb, *Z;
    float *cA, *cF, *cB, *wbuf;
    int* srcp;
    cudaGetSymbolAddress((void**)&srcp,  d_src);
    cudaGetSymbolAddress((void**)&xh,    d_xh);
    cudaGetSymbolAddress((void**)&aggh,  d_aggh);
    cudaGetSymbolAddress((void**)&xcath, d_xcath);
    cudaGetSymbolAddress((void**)&hAh,   d_hAh);
    cudaGetSymbolAddress((void**)&cA,    d_cA);
    cudaGetSymbolAddress((void**)&Pa,    d_Pa);
    cudaGetSymbolAddress((void**)&Pf,    d_Pf);
    cudaGetSymbolAddress((void**)&Pb,    d_Pb);
    cudaGetSymbolAddress((void**)&Z,     d_Z);
    cudaGetSymbolAddress((void**)&fwdh,  d_fwdh);
    cudaGetSymbolAddress((void**)&bwdph, d_bwdph);
    cudaGetSymbolAddress((void**)&cF,    d_cF);
    cudaGetSymbolAddress((void**)&cB,    d_cB);
    cudaGetSymbolAddress((void**)&wbuf,  d_w);
    cudaGetSymbolAddress((void**)&wh,    d_wh);

    __half* hWl1 = wh;                 __half* hWr1 = hWl1 + 16384;
    __half* hWl2 = hWr1 + 16384;       __half* hWr2 = hWl2 + 16384;
    __half* hWl3 = hWr2 + 16384;       __half* hWr3 = hWl3 + 16384;
    __half* hWih_a = hWr3 + 16384;     __half* hWhh_a = hWih_a + 65536;
    __half* hWih_f = hWhh_a + 65536;   __half* hWhh_f = hWih_f + 98304;
    __half* hWih_b = hWhh_f + 147456;  __half* hWhh_b = hWih_b + 98304;

    __half* h1h = xcath;
    __half* h2h = xcath + NN * CC;
    __half* h3h = xcath + 2 * NN * CC;
    float* out = (float*)d_out;

    cudaFuncSetAttribute(h16_gemm_kernel,
                         cudaFuncAttributeMaxDynamicSharedMemorySize, SMEM_BYTES);

    const int NH2_BLK = cdiv(NN * 64, 256);
    const int NC_BLK4 = cdiv(NN * CC / 4, 256);
    const int NJ_BLK4 = cdiv(NN * JKH / 4, 256);
    dim3 g128(cdiv(NN, BM), 1);
    dim3 g512(cdiv(NN, BM), 4);
    dim3 g768(cdiv(NN, BM), 6);
    dim3 g768x3(cdiv(3 * NN, BM), 6);

    // ---- prep: edge index + fp16 conversion (batched weights, 1 launch)
    detect_idx_kernel<<<1, 32>>>(ei);
    convert_src_kernel<<<cdiv(EE, 256), 256>>>(ei);
    cvt_half_kernel<<<cdiv(NN * CC / 4, 256), 256>>>(x, xh, NN * CC / 4);

    {
        CvtJobs jobs;
        const float* srcs[NSEG] = {Wl1, Wr1, Wl2, Wr2, Wl3, Wr3,
                                   Wih_a, Whh_a, Wih_f, Whh_f, Wih_b, Whh_b, nullptr};
        __half* dsts[NSEG] = {hWl1, hWr1, hWl2, hWr2, hWl3, hWr3,
                              hWih_a, hWhh_a, hWih_f, hWhh_f, hWih_b, hWhh_b, nullptr};
        int n4s[NSEG] = {4096, 4096, 4096, 4096, 4096, 4096,
                         16384, 16384, 24576, 36864, 24576, 36864, 0};
        int acc = 0;
        for (int s = 0; s < NSEG; ++s) {
            jobs.src[s] = srcs[s] ? srcs[s] : Wl1;
            jobs.dst[s] = dsts[s] ? dsts[s] : hWl1;
            acc += n4s[s];
            jobs.end4[s] = acc;
        }
        cvt_half_multi_kernel<<<cdiv(acc, 256), 256>>>(jobs, acc);
    }

    // ---- layer 1: mean SAGE + relu -> h1 (fp16)
    agg_mean_kernel<<<NH2_BLK, 256>>>(xh, aggh);
    h16_gemm_kernel<<<g128, 256, SMEM_BYTES>>>(aggh, xh, hWl1, hWr1, bl1,
                                               nullptr, h1h, NN, 128, 128, 128, 1);

    // ---- layer 2: max SAGE + relu -> h2 (fp16)
    agg_max_kernel<<<NH2_BLK, 256>>>(h1h, aggh);
    h16_gemm_kernel<<<g128, 256, SMEM_BYTES>>>(aggh, h1h, hWl2, hWr2, bl2,
                                               nullptr, h2h, NN, 128, 128, 128, 1);

    // ---- layer 3: LSTM aggregation (hoisted input projection, fp16 P/Z)
    h16_gemm_kernel<<<g512, 256, SMEM_BYTES>>>(h2h, nullptr, hWih_a, nullptr, nullptr,
                                               nullptr, Pa, NN, 512, 128, 0, 0);
    for (int t = 0; t < KK; ++t) {
        const __half* zr = nullptr;
        if (t > 0) {
            h16_gemm_kernel<<<g512, 256, SMEM_BYTES>>>(hAh, nullptr, hWhh_a, nullptr, nullptr,
                                                       nullptr, Z, NN, 512, 128, 0, 0);
            zr = Z;
        }
        lstm_gates_kernel<<<NC_BLK4, 256>>>(zr, Pa, srcp, t, bih_a, bhh_a,
                                            hAh, cA, 128, t == 0);
    }
    h16_gemm_kernel<<<g128, 256, SMEM_BYTES>>>(hAh, h2h, hWl3, hWr3, bl3,
                                               nullptr, h3h, NN, 128, 128, 128, 0);

    // ---- JK bi-LSTM: batched input projections (fp16 P)
    h16_gemm_kernel<<<g768x3, 256, SMEM_BYTES>>>(xcath, nullptr, hWih_f, nullptr, nullptr,
                                                 nullptr, Pf, 3 * NN, 768, 128, 0, 0);
    h16_gemm_kernel<<<g768x3, 256, SMEM_BYTES>>>(xcath, nullptr, hWih_b, nullptr, nullptr,
                                                 nullptr, Pb, 3 * NN, 768, 128, 0, 0);

    for (int t = 0; t < 3; ++t) {
        const __half* zrF = nullptr;
        if (t > 0) {
            h16_gemm_kernel<<<g768, 256, SMEM_BYTES>>>(
                fwdh + (size_t)(t - 1) * NN * JKH, nullptr, hWhh_f, nullptr, nullptr,
                nullptr, Z, NN, 768, JKH, 0, 0);
            zrF = Z;
        }
        lstm_gates_kernel<<<NJ_BLK4, 256>>>(zrF, Pf + (size_t)t * NN * 768, nullptr, 0,
                                            bih_f, bhh_f,
                                            fwdh + (size_t)t * NN * JKH, cF, JKH, t == 0);
        const __half* zrB = nullptr;
        if (t > 0) {
            h16_gemm_kernel<<<g768, 256, SMEM_BYTES>>>(
                bwdph + (size_t)(3 - t) * NN * JKH, nullptr, hWhh_b, nullptr, nullptr,
                nullptr, Z, NN, 768, JKH, 0, 0);
            zrB = Z;
        }
        lstm_gates_kernel<<<NJ_BLK4, 256>>>(zrB, Pb + (size_t)(2 - t) * NN * 768, nullptr, 0,
                                            bih_b, bhh_b,
                                            bwdph + (size_t)(2 - t) * NN * JKH, cB, JKH, t == 0);
    }

    // ---- attention + combine
    jk_score_kernel<<<cdiv(NN * 32, 256), 256>>>(att_w, att_b, wbuf);
    jk_combine_kernel<<<NH2_BLK, 256>>>(out);

    (void)out_size;
}